// round 1
// baseline (speedup 1.0000x reference)
#include <cuda_runtime.h>
#include <math.h>
#include <cstddef>

// ---------------------------------------------------------------------------
// Problem constants
// ---------------------------------------------------------------------------
namespace {
constexpr int BATCH = 4, HGT = 96, WID = 96, CH = 384, HDIM = 128;
constexpr int NPIX = BATCH * HGT * WID;   // 36864
constexpr int MLPH = 4 * CH;              // 1536
constexpr float ATTN_SCALE = 0.15430334996209191f; // (128//3)^-0.5 = 42^-0.5
// attention smem: Q,K,V padded rows of 132 floats + S (96x96)
constexpr int QKV_PAD = 132;
constexpr int ATTN_SMEM_BYTES = (3 * 96 * QKV_PAD + 96 * 96) * 4; // 188928
}

// ---------------------------------------------------------------------------
// Scratch (device globals: allowed; cudaMalloc is not)
// ---------------------------------------------------------------------------
__device__ float g_gates[NPIX * 6];                   // per-branch 2-way gates
__device__ float g_moe[(size_t)NPIX * HDIM];
__device__ float g_qkv[(size_t)NPIX * 3 * HDIM];
__device__ float g_obuf[(size_t)NPIX * HDIM];
__device__ float g_xc[(size_t)NPIX * CH];
__device__ float g_mgate[NPIX * 3];                   // top-2 MoE gates
__device__ float g_hidden[(size_t)NPIX * MLPH];
__device__ float g_accum[(size_t)NPIX * CH];

__device__ __forceinline__ float gelu_f(float v) {
    float u = 0.7978845608028654f * (v + 0.044715f * v * v * v);
    return 0.5f * v * (1.0f + tanhf(u));
}

// ---------------------------------------------------------------------------
// Branch gating: g[pix][br][2] = softmax(x_br . wg_br)  (warp per pixel)
// ---------------------------------------------------------------------------
__device__ __forceinline__ void bg_dot(const float* xp, const float* wg, int lane,
                                       float& g0, float& g1) {
    float a0 = 0.f, a1 = 0.f;
#pragma unroll
    for (int i = 0; i < 4; i++) {
        int c = i * 32 + lane;
        float xv = xp[c];
        a0 += xv * wg[c * 2 + 0];
        a1 += xv * wg[c * 2 + 1];
    }
#pragma unroll
    for (int o = 16; o > 0; o >>= 1) {
        a0 += __shfl_xor_sync(0xffffffffu, a0, o);
        a1 += __shfl_xor_sync(0xffffffffu, a1, o);
    }
    float m = fmaxf(a0, a1);
    float e0 = expf(a0 - m), e1 = expf(a1 - m);
    float inv = 1.0f / (e0 + e1);
    g0 = e0 * inv;
    g1 = e1 * inv;
}

__global__ __launch_bounds__(256) void branch_gate_kernel(
    const float* __restrict__ x, const float* __restrict__ wg1,
    const float* __restrict__ wg2, const float* __restrict__ wg3,
    float* __restrict__ gates) {
    int gid = blockIdx.x * blockDim.x + threadIdx.x;
    int pix = gid >> 5;
    int lane = gid & 31;
    if (pix >= NPIX) return;
    const float* xp = x + (size_t)pix * CH;
    float g0, g1;
    bg_dot(xp + 0 * HDIM, wg1, lane, g0, g1);
    if (lane == 0) { gates[pix * 6 + 0] = g0; gates[pix * 6 + 1] = g1; }
    bg_dot(xp + 1 * HDIM, wg2, lane, g0, g1);
    if (lane == 0) { gates[pix * 6 + 2] = g0; gates[pix * 6 + 3] = g1; }
    bg_dot(xp + 2 * HDIM, wg3, lane, g0, g1);
    if (lane == 0) { gates[pix * 6 + 4] = g0; gates[pix * 6 + 5] = g1; }
}

// ---------------------------------------------------------------------------
// Fused dual-conv + gate:  moe = g0*(convA(x)+ba) + g1*(convB(x)+bb)
// Block: 32 consecutive w-pixels (fixed b,h) x 128 channels. 18 taps.
// Gate is folded into the A-tile load so a single accumulator set suffices.
// ---------------------------------------------------------------------------
__global__ __launch_bounds__(256) void conv_moe_kernel(
    const float* __restrict__ x,
    const float* __restrict__ wa, const float* __restrict__ ba,
    const float* __restrict__ wb, const float* __restrict__ bb,
    const float* __restrict__ gates, int br, float* __restrict__ moe) {
    __shared__ float sA[32 * 128];
    __shared__ float sW[32 * 128];
    __shared__ float sGA[32], sGB[32];

    int tid = threadIdx.x;
    int wc = blockIdx.x % 3;
    int h = blockIdx.x / 3;
    int b = blockIdx.y;
    int w0 = wc * 32;
    int pixbase = (b * HGT + h) * WID + w0;

    if (tid < 32) {
        sGA[tid] = gates[(size_t)(pixbase + tid) * 6 + br * 2 + 0];
        sGB[tid] = gates[(size_t)(pixbase + tid) * 6 + br * 2 + 1];
    }
    __syncthreads();

    float acc[4][4] = {};
    int tx = tid & 31, ty = tid >> 5;   // c = tx*4, p = ty*4..

    for (int t = 0; t < 18; t++) {
        int tc = t % 9;
        int isB = (t >= 9);
        int dh, dw;
        if (br == 0)      { dh = tc / 3 - 1; dw = tc % 3 - 1; }
        else if (br == 1) { dh = tc - 4;     dw = 0;          }
        else              { dh = 0;          dw = tc - 4;     }
        if (isB) { dh *= 2; dw *= 2; }
        const float* wt = (isB ? wb : wa) + (size_t)tc * (HDIM * HDIM);
        int hh = h + dh;
        const float* gsel = isB ? sGB : sGA;

        // load shifted, gate-scaled A tile (32 pixels x 128 ch)
#pragma unroll
        for (int l = 0; l < 4; l++) {
            int f = tid + l * 256;          // float4 index 0..1023
            int p = f >> 5;
            int c = (f & 31) * 4;
            float4 v = make_float4(0.f, 0.f, 0.f, 0.f);
            int wwv = w0 + p + dw;
            if (hh >= 0 && hh < HGT && wwv >= 0 && wwv < WID) {
                v = *(const float4*)&x[((size_t)((b * HGT + hh) * WID + wwv)) * CH +
                                       br * HDIM + c];
            }
            float gg = gsel[p];
            v.x *= gg; v.y *= gg; v.z *= gg; v.w *= gg;
            *(float4*)&sA[p * 128 + c] = v;
        }

        for (int chb = 0; chb < 4; chb++) {
#pragma unroll
            for (int l = 0; l < 4; l++) {
                int f = tid + l * 256;
                int kk = f >> 5;
                int c = (f & 31) * 4;
                *(float4*)&sW[kk * 128 + c] =
                    *(const float4*)&wt[(size_t)(chb * 32 + kk) * HDIM + c];
            }
            __syncthreads();
#pragma unroll
            for (int kk = 0; kk < 32; kk++) {
                int k = chb * 32 + kk;
                float a[4];
                a[0] = sA[(ty * 4 + 0) * 128 + k];
                a[1] = sA[(ty * 4 + 1) * 128 + k];
                a[2] = sA[(ty * 4 + 2) * 128 + k];
                a[3] = sA[(ty * 4 + 3) * 128 + k];
                float4 w4 = *(const float4*)&sW[kk * 128 + tx * 4];
                float wv[4] = {w4.x, w4.y, w4.z, w4.w};
#pragma unroll
                for (int i = 0; i < 4; i++)
#pragma unroll
                    for (int j = 0; j < 4; j++) acc[i][j] += a[i] * wv[j];
            }
            __syncthreads();
        }
    }

    // epilogue: gated biases, write moe
    int c0 = tx * 4;
#pragma unroll
    for (int pp = 0; pp < 4; pp++) {
        int p = ty * 4 + pp;
        float gg0 = sGA[p], gg1 = sGB[p];
        float4 o;
        o.x = acc[pp][0] + gg0 * ba[c0 + 0] + gg1 * bb[c0 + 0];
        o.y = acc[pp][1] + gg0 * ba[c0 + 1] + gg1 * bb[c0 + 1];
        o.z = acc[pp][2] + gg0 * ba[c0 + 2] + gg1 * bb[c0 + 2];
        o.w = acc[pp][3] + gg0 * ba[c0 + 3] + gg1 * bb[c0 + 3];
        *(float4*)&moe[(size_t)(pixbase + p) * HDIM + c0] = o;
    }
}

// ---------------------------------------------------------------------------
// Generic fp32 tiled GEMM: C = post(A@B + bias) with optional gelu,
// per-row scale (MoE gate) and accumulate. BM=BN=64, BK=16, 256 threads, 4x4.
// All M,N,K used are multiples of the tile -> no bounds checks.
// ---------------------------------------------------------------------------
__global__ __launch_bounds__(256) void gemm_kernel(
    const float* __restrict__ A, int lda,
    const float* __restrict__ B, int ldb,
    const float* __restrict__ bias,
    const float* __restrict__ rowscale, int rs_stride, int rs_off,
    float* __restrict__ Cp, int ldc, int K, int doGelu, int doAccum) {
    __shared__ float sA[16][68];
    __shared__ float sB[16][68];
    int tid = threadIdx.x;
    int m0 = blockIdx.y * 64;
    int n0 = blockIdx.x * 64;
    int tx = tid & 15, ty = tid >> 4;

    float acc[4][4] = {};

    int la_m = tid >> 2;            // 0..63
    int la_k = (tid & 3) * 4;       // 0,4,8,12
    int lb_k = tid >> 4;            // 0..15
    int lb_n = (tid & 15) * 4;      // 0..60
    const float* Aptr = A + (size_t)(m0 + la_m) * lda + la_k;
    const float* Bptr = B + (size_t)lb_k * ldb + n0 + lb_n;

    for (int k0 = 0; k0 < K; k0 += 16) {
        float4 av = *(const float4*)(Aptr + k0);
        sA[la_k + 0][la_m] = av.x;
        sA[la_k + 1][la_m] = av.y;
        sA[la_k + 2][la_m] = av.z;
        sA[la_k + 3][la_m] = av.w;
        *(float4*)&sB[lb_k][lb_n] = *(const float4*)(Bptr + (size_t)k0 * ldb);
        __syncthreads();
#pragma unroll
        for (int kk = 0; kk < 16; kk++) {
            float4 a4 = *(const float4*)&sA[kk][ty * 4];
            float4 b4 = *(const float4*)&sB[kk][tx * 4];
            float a[4] = {a4.x, a4.y, a4.z, a4.w};
            float bv[4] = {b4.x, b4.y, b4.z, b4.w};
#pragma unroll
            for (int i = 0; i < 4; i++)
#pragma unroll
                for (int j = 0; j < 4; j++) acc[i][j] += a[i] * bv[j];
        }
        __syncthreads();
    }

    int nn = n0 + tx * 4;
    float bv[4] = {0.f, 0.f, 0.f, 0.f};
    if (bias) {
        bv[0] = bias[nn + 0]; bv[1] = bias[nn + 1];
        bv[2] = bias[nn + 2]; bv[3] = bias[nn + 3];
    }
#pragma unroll
    for (int i = 0; i < 4; i++) {
        int mm = m0 + ty * 4 + i;
        float scl = rowscale ? rowscale[(size_t)mm * rs_stride + rs_off] : 1.0f;
        float v[4];
#pragma unroll
        for (int j = 0; j < 4; j++) {
            float t = acc[i][j] + bv[j];
            if (doGelu) t = gelu_f(t);
            v[j] = t * scl;
        }
        float* cp = &Cp[(size_t)mm * ldc + nn];
        float4 o;
        if (doAccum) {
            float4 old = *(const float4*)cp;
            o = make_float4(old.x + v[0], old.y + v[1], old.z + v[2], old.w + v[3]);
        } else {
            o = make_float4(v[0], v[1], v[2], v[3]);
        }
        *(float4*)cp = o;
    }
}

// ---------------------------------------------------------------------------
// Attention over the W axis per (b,h) row. One block per (b,h): 384 blocks.
// S = softmax(Q K^T * scale); O = S V; write spatially transposed:
// obuf[b, q, h, c] = O[q][c]
// ---------------------------------------------------------------------------
__global__ __launch_bounds__(256) void attn_kernel(
    const float* __restrict__ qkv, float* __restrict__ obuf) {
    extern __shared__ float sm[];
    float* Qs = sm;
    float* Ks = sm + 96 * QKV_PAD;
    float* Vs = sm + 2 * 96 * QKV_PAD;
    float* Ss = sm + 3 * 96 * QKV_PAD;

    int bh = blockIdx.x;
    int b = bh / 96, h = bh % 96;
    int tid = threadIdx.x;
    const float* base = qkv + (size_t)bh * 96 * 384;

    for (int f = tid; f < 96 * 96; f += 256) {   // 96 pixels x 96 float4
        int p = f / 96;
        int q = f % 96;
        int c = q * 4;
        float4 v = *(const float4*)&base[(size_t)p * 384 + c];
        float* dst;
        if (c < 128)      dst = &Qs[p * QKV_PAD + c];
        else if (c < 256) dst = &Ks[p * QKV_PAD + c - 128];
        else              dst = &Vs[p * QKV_PAD + c - 256];
        *(float4*)dst = v;
    }
    __syncthreads();

    // phase 1: S = Q K^T * scale (96x96x128), 6x6 micro-tile
    {
        int tx = tid & 15, ty = tid >> 4;
        int q0 = ty * 6, j0 = tx * 6;
        float acc[6][6] = {};
        for (int k = 0; k < 128; k += 4) {
            float4 qa[6];
#pragma unroll
            for (int i = 0; i < 6; i++)
                qa[i] = *(const float4*)&Qs[(q0 + i) * QKV_PAD + k];
#pragma unroll
            for (int j = 0; j < 6; j++) {
                float4 kv = *(const float4*)&Ks[(j0 + j) * QKV_PAD + k];
#pragma unroll
                for (int i = 0; i < 6; i++)
                    acc[i][j] += qa[i].x * kv.x + qa[i].y * kv.y +
                                 qa[i].z * kv.z + qa[i].w * kv.w;
            }
        }
#pragma unroll
        for (int i = 0; i < 6; i++)
#pragma unroll
            for (int j = 0; j < 6; j++)
                Ss[(q0 + i) * 96 + j0 + j] = acc[i][j] * ATTN_SCALE;
    }
    __syncthreads();

    // phase 2: row softmax (warp per row)
    {
        int wid = tid >> 5, lane = tid & 31;
        for (int r = wid; r < 96; r += 8) {
            float v0 = Ss[r * 96 + lane];
            float v1 = Ss[r * 96 + 32 + lane];
            float v2 = Ss[r * 96 + 64 + lane];
            float m = fmaxf(v0, fmaxf(v1, v2));
#pragma unroll
            for (int o = 16; o > 0; o >>= 1)
                m = fmaxf(m, __shfl_xor_sync(0xffffffffu, m, o));
            float e0 = expf(v0 - m), e1 = expf(v1 - m), e2 = expf(v2 - m);
            float s = e0 + e1 + e2;
#pragma unroll
            for (int o = 16; o > 0; o >>= 1)
                s += __shfl_xor_sync(0xffffffffu, s, o);
            float inv = 1.0f / s;
            Ss[r * 96 + lane] = e0 * inv;
            Ss[r * 96 + 32 + lane] = e1 * inv;
            Ss[r * 96 + 64 + lane] = e2 * inv;
        }
    }
    __syncthreads();

    // phase 3: O = S V (96x128x96), 6x8 micro-tile; transposed store
    {
        int tx = tid & 15, ty = tid >> 4;
        int c0 = tx * 8, q0 = ty * 6;
        float acc[6][8] = {};
        for (int k = 0; k < 96; k++) {
            float4 va = *(const float4*)&Vs[k * QKV_PAD + c0];
            float4 vb = *(const float4*)&Vs[k * QKV_PAD + c0 + 4];
#pragma unroll
            for (int i = 0; i < 6; i++) {
                float p = Ss[(q0 + i) * 96 + k];
                acc[i][0] += p * va.x; acc[i][1] += p * va.y;
                acc[i][2] += p * va.z; acc[i][3] += p * va.w;
                acc[i][4] += p * vb.x; acc[i][5] += p * vb.y;
                acc[i][6] += p * vb.z; acc[i][7] += p * vb.w;
            }
        }
#pragma unroll
        for (int i = 0; i < 6; i++) {
            int opix = (b * 96 + (q0 + i)) * 96 + h;   // spatial transpose
            float* dst = &obuf[(size_t)opix * HDIM + c0];
            *(float4*)dst = make_float4(acc[i][0], acc[i][1], acc[i][2], acc[i][3]);
            *(float4*)(dst + 4) = make_float4(acc[i][4], acc[i][5], acc[i][6], acc[i][7]);
        }
    }
}

// ---------------------------------------------------------------------------
// MoE top-2 gating from xc: logits = xc @ wg_final (384->3), top-2 softmax.
// Warp per pixel. Tie-break matches lax.top_k (lower index wins).
// ---------------------------------------------------------------------------
__global__ __launch_bounds__(256) void moe_gate_kernel(
    const float* __restrict__ xc, const float* __restrict__ wgf,
    float* __restrict__ mg) {
    int gid = blockIdx.x * blockDim.x + threadIdx.x;
    int pix = gid >> 5;
    int lane = gid & 31;
    if (pix >= NPIX) return;
    const float* xp = xc + (size_t)pix * CH;
    float l0 = 0.f, l1 = 0.f, l2 = 0.f;
#pragma unroll
    for (int i = 0; i < 12; i++) {
        int c = i * 32 + lane;
        float xv = xp[c];
        l0 += xv * wgf[c * 3 + 0];
        l1 += xv * wgf[c * 3 + 1];
        l2 += xv * wgf[c * 3 + 2];
    }
#pragma unroll
    for (int o = 16; o > 0; o >>= 1) {
        l0 += __shfl_xor_sync(0xffffffffu, l0, o);
        l1 += __shfl_xor_sync(0xffffffffu, l1, o);
        l2 += __shfl_xor_sync(0xffffffffu, l2, o);
    }
    if (lane == 0) {
        float l[3] = {l0, l1, l2};
        int i0 = 0;
        if (l[1] > l[i0]) i0 = 1;
        if (l[2] > l[i0]) i0 = 2;
        int i1 = -1;
        for (int j = 0; j < 3; j++)
            if (j != i0 && (i1 < 0 || l[j] > l[i1])) i1 = j;
        float e1 = expf(l[i1] - l[i0]);
        float inv = 1.0f / (1.0f + e1);
        float g[3] = {0.f, 0.f, 0.f};
        g[i0] = inv;
        g[i1] = e1 * inv;
        mg[pix * 3 + 0] = g[0];
        mg[pix * 3 + 1] = g[1];
        mg[pix * 3 + 2] = g[2];
    }
}

// ---------------------------------------------------------------------------
// Host launcher
// ---------------------------------------------------------------------------
extern "C" void kernel_launch(void* const* d_in, const int* in_sizes, int n_in,
                              void* d_out, int out_size) {
    (void)in_sizes; (void)n_in; (void)out_size;
    const float* x = (const float*)d_in[0];
    const float* w_conv[6] = {(const float*)d_in[1], (const float*)d_in[3],
                              (const float*)d_in[5], (const float*)d_in[7],
                              (const float*)d_in[9], (const float*)d_in[11]};
    const float* b_conv[6] = {(const float*)d_in[2], (const float*)d_in[4],
                              (const float*)d_in[6], (const float*)d_in[8],
                              (const float*)d_in[10], (const float*)d_in[12]};
    const float* wg1 = (const float*)d_in[13];
    const float* wg2 = (const float*)d_in[14];
    const float* wg3 = (const float*)d_in[15];
    const float* w_qkv = (const float*)d_in[16];   // (3,128,384)
    const float* w_ap  = (const float*)d_in[17];   // (3,128,128)
    const float* b_ap  = (const float*)d_in[18];   // (3,128)
    const float* wgf   = (const float*)d_in[19];   // (384,3)
    const float* w1    = (const float*)d_in[20];   // (3,384,1536)
    const float* b1    = (const float*)d_in[21];   // (3,1536)
    const float* w2    = (const float*)d_in[22];   // (3,1536,384)
    const float* b2    = (const float*)d_in[23];   // (3,384)
    const float* wp    = (const float*)d_in[24];   // (384,384)
    const float* bp    = (const float*)d_in[25];   // (384)
    float* out = (float*)d_out;

    float *gates, *moe, *qkv, *obuf, *xc, *mgate, *hidden, *accum;
    cudaGetSymbolAddress((void**)&gates, g_gates);
    cudaGetSymbolAddress((void**)&moe, g_moe);
    cudaGetSymbolAddress((void**)&qkv, g_qkv);
    cudaGetSymbolAddress((void**)&obuf, g_obuf);
    cudaGetSymbolAddress((void**)&xc, g_xc);
    cudaGetSymbolAddress((void**)&mgate, g_mgate);
    cudaGetSymbolAddress((void**)&hidden, g_hidden);
    cudaGetSymbolAddress((void**)&accum, g_accum);

    cudaFuncSetAttribute(attn_kernel, cudaFuncAttributeMaxDynamicSharedMemorySize,
                         ATTN_SMEM_BYTES);

    // 1. per-branch 2-way gates
    branch_gate_kernel<<<NPIX / 8, 256>>>(x, wg1, wg2, wg3, gates);

    // 2. branches: dual-conv+gate -> qkv -> attention -> proj into xc
    for (int br = 0; br < 3; br++) {
        conv_moe_kernel<<<dim3(3 * HGT, BATCH), 256>>>(
            x, w_conv[2 * br], b_conv[2 * br], w_conv[2 * br + 1],
            b_conv[2 * br + 1], gates, br, moe);
        gemm_kernel<<<dim3((3 * HDIM) / 64, NPIX / 64), 256>>>(
            moe, HDIM, w_qkv + (size_t)br * HDIM * 3 * HDIM, 3 * HDIM,
            nullptr, nullptr, 0, 0, qkv, 3 * HDIM, HDIM, 0, 0);
        attn_kernel<<<BATCH * HGT, 256, ATTN_SMEM_BYTES>>>(qkv, obuf);
        gemm_kernel<<<dim3(HDIM / 64, NPIX / 64), 256>>>(
            obuf, HDIM, w_ap + (size_t)br * HDIM * HDIM, HDIM,
            b_ap + (size_t)br * HDIM, nullptr, 0, 0,
            xc + br * HDIM, CH, HDIM, 0, 0);
    }

    // 3. top-2 MoE gates
    moe_gate_kernel<<<NPIX / 8, 256>>>(xc, wgf, mgate);

    // 4. dense 3-expert MLP with gated accumulation
    for (int e = 0; e < 3; e++) {
        gemm_kernel<<<dim3(MLPH / 64, NPIX / 64), 256>>>(
            xc, CH, w1 + (size_t)e * CH * MLPH, MLPH, b1 + (size_t)e * MLPH,
            nullptr, 0, 0, hidden, MLPH, CH, 1, 0);
        gemm_kernel<<<dim3(CH / 64, NPIX / 64), 256>>>(
            hidden, MLPH, w2 + (size_t)e * MLPH * CH, CH, b2 + (size_t)e * CH,
            mgate, 3, e, accum, CH, MLPH, 0, (e > 0) ? 1 : 0);
    }

    // 5. final projection -> output
    gemm_kernel<<<dim3(CH / 64, NPIX / 64), 256>>>(
        accum, CH, wp, CH, bp, nullptr, 0, 0, out, CH, CH, 0, 0);
}

// round 3
// speedup vs baseline: 2.7753x; 2.7753x over previous
#include <cuda_runtime.h>
#include <math.h>
#include <cstddef>

// ---------------------------------------------------------------------------
// Problem constants
// ---------------------------------------------------------------------------
namespace {
constexpr int BATCH = 4, HGT = 96, WID = 96, CH = 384, HDIM = 128;
constexpr int NPIX = BATCH * HGT * WID;   // 36864
constexpr int MLPH = 4 * CH;              // 1536
constexpr float ATTN_SCALE = 0.15430334996209191f; // (128//3)^-0.5 = 42^-0.5
constexpr int QKV_PAD = 132;
constexpr int ATTN_SMEM_BYTES = (3 * 96 * QKV_PAD + 96 * 96) * 4; // 188928
constexpr int CONV_SMEM_BYTES = (32 * 132 + 64 * 132) * 4;        // 50688
}

// ---------------------------------------------------------------------------
// Scratch (device globals)
// ---------------------------------------------------------------------------
__device__ float g_gates[NPIX * 6];
__device__ float g_moe[(size_t)NPIX * HDIM];
__device__ float g_qkv[(size_t)NPIX * 3 * HDIM];
__device__ float g_obuf[(size_t)NPIX * HDIM];
__device__ float g_xc[(size_t)NPIX * CH];
__device__ float g_mgate[NPIX * 3];
__device__ float g_hidden[(size_t)NPIX * MLPH];
__device__ float g_accum[(size_t)NPIX * CH];

__device__ __forceinline__ float gelu_f(float v) {
    float u = 0.7978845608028654f * (v + 0.044715f * v * v * v);
    return 0.5f * v * (1.0f + tanhf(u));
}

// tf32 round-to-nearest conversion (half the error of truncation)
__device__ __forceinline__ unsigned f2t(float f) {
    unsigned u;
    asm("cvt.rna.tf32.f32 %0, %1;" : "=r"(u) : "f"(f));
    return u;
}

// m16n8k8 tf32 mma: D = A@B + D
__device__ __forceinline__ void mma8(float* c, const unsigned* a, const unsigned* b) {
    asm volatile(
        "mma.sync.aligned.m16n8k8.row.col.f32.tf32.tf32.f32 "
        "{%0,%1,%2,%3}, {%4,%5,%6,%7}, {%8,%9}, {%0,%1,%2,%3};"
        : "+f"(c[0]), "+f"(c[1]), "+f"(c[2]), "+f"(c[3])
        : "r"(a[0]), "r"(a[1]), "r"(a[2]), "r"(a[3]), "r"(b[0]), "r"(b[1]));
}

// ---------------------------------------------------------------------------
// Branch gating (warp per pixel)
// ---------------------------------------------------------------------------
__device__ __forceinline__ void bg_dot(const float* xp, const float* wg, int lane,
                                       float& g0, float& g1) {
    float a0 = 0.f, a1 = 0.f;
#pragma unroll
    for (int i = 0; i < 4; i++) {
        int c = i * 32 + lane;
        float xv = xp[c];
        a0 += xv * wg[c * 2 + 0];
        a1 += xv * wg[c * 2 + 1];
    }
#pragma unroll
    for (int o = 16; o > 0; o >>= 1) {
        a0 += __shfl_xor_sync(0xffffffffu, a0, o);
        a1 += __shfl_xor_sync(0xffffffffu, a1, o);
    }
    float m = fmaxf(a0, a1);
    float e0 = expf(a0 - m), e1 = expf(a1 - m);
    float inv = 1.0f / (e0 + e1);
    g0 = e0 * inv;
    g1 = e1 * inv;
}

__global__ __launch_bounds__(256) void branch_gate_kernel(
    const float* __restrict__ x, const float* __restrict__ wg1,
    const float* __restrict__ wg2, const float* __restrict__ wg3,
    float* __restrict__ gates) {
    int gid = blockIdx.x * blockDim.x + threadIdx.x;
    int pix = gid >> 5;
    int lane = gid & 31;
    if (pix >= NPIX) return;
    const float* xp = x + (size_t)pix * CH;
    float g0, g1;
    bg_dot(xp + 0 * HDIM, wg1, lane, g0, g1);
    if (lane == 0) { gates[pix * 6 + 0] = g0; gates[pix * 6 + 1] = g1; }
    bg_dot(xp + 1 * HDIM, wg2, lane, g0, g1);
    if (lane == 0) { gates[pix * 6 + 2] = g0; gates[pix * 6 + 3] = g1; }
    bg_dot(xp + 2 * HDIM, wg3, lane, g0, g1);
    if (lane == 0) { gates[pix * 6 + 4] = g0; gates[pix * 6 + 5] = g1; }
}

// ---------------------------------------------------------------------------
// Fused dual-conv + gate on tensor cores.
// Block: 32 w-pixels x 128 out-channels. 18 taps, K=128 per tap.
// A tile (gate-scaled, shifted x) in smem [32][132]; W chunked [64][132].
// 8 warps: warp tile 32x16 (MFRAG=2 m16, NFRAG=2 n8).
// ---------------------------------------------------------------------------
__global__ __launch_bounds__(256) void conv_moe_tc(
    const float* __restrict__ x,
    const float* __restrict__ wa, const float* __restrict__ ba,
    const float* __restrict__ wb, const float* __restrict__ bb,
    const float* __restrict__ gates, int br, float* __restrict__ moe) {
    extern __shared__ unsigned cm[];
    unsigned* sA = cm;              // 32*132
    unsigned* sW = cm + 32 * 132;   // 64*132
    __shared__ float sGA[32], sGB[32];

    int tid = threadIdx.x;
    int lane = tid & 31, wid = tid >> 5;
    int gid = lane >> 2, tig = lane & 3;
    int wn = wid * 16;

    int wc = blockIdx.x % 3;
    int h = blockIdx.x / 3;
    int b = blockIdx.y;
    int w0 = wc * 32;
    int pixbase = (b * HGT + h) * WID + w0;

    if (tid < 32) {
        sGA[tid] = gates[(size_t)(pixbase + tid) * 6 + br * 2 + 0];
        sGB[tid] = gates[(size_t)(pixbase + tid) * 6 + br * 2 + 1];
    }
    __syncthreads();

    float acc[2][2][4] = {};

    for (int t = 0; t < 18; t++) {
        int tc = t % 9;
        int isB = (t >= 9);
        int dh, dw;
        if (br == 0)      { dh = tc / 3 - 1; dw = tc % 3 - 1; }
        else if (br == 1) { dh = tc - 4;     dw = 0;          }
        else              { dh = 0;          dw = tc - 4;     }
        if (isB) { dh *= 2; dw *= 2; }
        const float* wt = (isB ? wb : wa) + (size_t)tc * (HDIM * HDIM);
        int hh = h + dh;
        const float* gsel = isB ? sGB : sGA;

        // gate-scaled shifted A tile, tf32-rounded
#pragma unroll
        for (int l = 0; l < 4; l++) {
            int f = tid + l * 256;
            int p = f >> 5;
            int ks = (f & 31) * 4;
            float4 v = make_float4(0.f, 0.f, 0.f, 0.f);
            int wwv = w0 + p + dw;
            if (hh >= 0 && hh < HGT && wwv >= 0 && wwv < WID) {
                v = *(const float4*)&x[((size_t)((b * HGT + hh) * WID + wwv)) * CH +
                                       br * HDIM + ks];
            }
            float gg = gsel[p];
            uint4 u;
            u.x = f2t(v.x * gg); u.y = f2t(v.y * gg);
            u.z = f2t(v.z * gg); u.w = f2t(v.w * gg);
            *(uint4*)&sA[p * 132 + ks] = u;
        }

        for (int chunk = 0; chunk < 2; chunk++) {
            // load W chunk: 64 k-rows x 128 n
#pragma unroll
            for (int l = 0; l < 8; l++) {
                int f = tid + l * 256;
                int k = f >> 5;
                int ns = (f & 31) * 4;
                float4 v = *(const float4*)&wt[(size_t)(chunk * 64 + k) * HDIM + ns];
                uint4 u;
                u.x = f2t(v.x); u.y = f2t(v.y); u.z = f2t(v.z); u.w = f2t(v.w);
                *(uint4*)&sW[k * 132 + ns] = u;
            }
            __syncthreads();
#pragma unroll
            for (int kk = 0; kk < 64; kk += 8) {
                int kg = chunk * 64 + kk;
                unsigned a[2][4], bfr[2][2];
#pragma unroll
                for (int mi = 0; mi < 2; mi++) {
                    int r = mi * 16 + gid;
                    a[mi][0] = sA[r * 132 + kg + tig];
                    a[mi][1] = sA[(r + 8) * 132 + kg + tig];
                    a[mi][2] = sA[r * 132 + kg + tig + 4];
                    a[mi][3] = sA[(r + 8) * 132 + kg + tig + 4];
                }
#pragma unroll
                for (int ni = 0; ni < 2; ni++) {
                    int c = wn + ni * 8 + gid;
                    bfr[ni][0] = sW[(kk + tig) * 132 + c];
                    bfr[ni][1] = sW[(kk + tig + 4) * 132 + c];
                }
#pragma unroll
                for (int mi = 0; mi < 2; mi++)
#pragma unroll
                    for (int ni = 0; ni < 2; ni++)
                        mma8(acc[mi][ni], a[mi], bfr[ni]);
            }
            __syncthreads();
        }
    }

    // epilogue: gated biases, float2 stores
#pragma unroll
    for (int mi = 0; mi < 2; mi++) {
#pragma unroll
        for (int half = 0; half < 2; half++) {
            int p = mi * 16 + gid + half * 8;
            float gg0 = sGA[p], gg1 = sGB[p];
#pragma unroll
            for (int ni = 0; ni < 2; ni++) {
                int c = wn + ni * 8 + tig * 2;
                float v0 = acc[mi][ni][half * 2 + 0] + gg0 * ba[c] + gg1 * bb[c];
                float v1 = acc[mi][ni][half * 2 + 1] + gg0 * ba[c + 1] + gg1 * bb[c + 1];
                *(float2*)&moe[(size_t)(pixbase + p) * HDIM + c] = make_float2(v0, v1);
            }
        }
    }
}

// ---------------------------------------------------------------------------
// Tensor-core fp32-in/out GEMM (tf32 internally).
// C = post(A@B + bias) with optional gelu, rowscale, accumulate.
// BM=BN=128, BK=32, 256 threads, warp grid 2x4 (warp tile 64x32).
// All M,N mult of 128; K mult of 32.
// ---------------------------------------------------------------------------
__global__ __launch_bounds__(256, 2) void gemm_tc(
    const float* __restrict__ A, int lda,
    const float* __restrict__ B, int ldb,
    const float* __restrict__ bias,
    const float* __restrict__ rowscale, int rs_stride, int rs_off,
    float* __restrict__ Cp, int ldc, int K, int doGelu, int doAccum) {
    __shared__ unsigned sA[128 * 36];
    __shared__ unsigned sB[32 * 132];
    int tid = threadIdx.x;
    int lane = tid & 31, wid = tid >> 5;
    int gid = lane >> 2, tig = lane & 3;
    int wm = (wid >> 2) * 64, wn = (wid & 3) * 32;
    int m0 = blockIdx.y * 128, n0 = blockIdx.x * 128;

    float acc[4][4][4] = {};

    for (int k0 = 0; k0 < K; k0 += 32) {
#pragma unroll
        for (int l = 0; l < 4; l++) {
            int f = tid + l * 256;
            int m = f >> 3;
            int ks = (f & 7) * 4;
            float4 v = *(const float4*)&A[(size_t)(m0 + m) * lda + k0 + ks];
            uint4 u;
            u.x = f2t(v.x); u.y = f2t(v.y); u.z = f2t(v.z); u.w = f2t(v.w);
            *(uint4*)&sA[m * 36 + ks] = u;
        }
#pragma unroll
        for (int l = 0; l < 4; l++) {
            int f = tid + l * 256;
            int k = f >> 5;
            int ns = (f & 31) * 4;
            float4 v = *(const float4*)&B[(size_t)(k0 + k) * ldb + n0 + ns];
            uint4 u;
            u.x = f2t(v.x); u.y = f2t(v.y); u.z = f2t(v.z); u.w = f2t(v.w);
            *(uint4*)&sB[k * 132 + ns] = u;
        }
        __syncthreads();
#pragma unroll
        for (int kk = 0; kk < 32; kk += 8) {
            unsigned a[4][4], bfr[4][2];
#pragma unroll
            for (int mi = 0; mi < 4; mi++) {
                int r = wm + mi * 16 + gid;
                a[mi][0] = sA[r * 36 + kk + tig];
                a[mi][1] = sA[(r + 8) * 36 + kk + tig];
                a[mi][2] = sA[r * 36 + kk + tig + 4];
                a[mi][3] = sA[(r + 8) * 36 + kk + tig + 4];
            }
#pragma unroll
            for (int ni = 0; ni < 4; ni++) {
                int c = wn + ni * 8 + gid;
                bfr[ni][0] = sB[(kk + tig) * 132 + c];
                bfr[ni][1] = sB[(kk + tig + 4) * 132 + c];
            }
#pragma unroll
            for (int mi = 0; mi < 4; mi++)
#pragma unroll
                for (int ni = 0; ni < 4; ni++)
                    mma8(acc[mi][ni], a[mi], bfr[ni]);
        }
        __syncthreads();
    }

    // epilogue
#pragma unroll
    for (int mi = 0; mi < 4; mi++) {
#pragma unroll
        for (int half = 0; half < 2; half++) {
            int r = m0 + wm + mi * 16 + gid + half * 8;
            float scl = rowscale ? rowscale[(size_t)r * rs_stride + rs_off] : 1.0f;
#pragma unroll
            for (int ni = 0; ni < 4; ni++) {
                int c = n0 + wn + ni * 8 + tig * 2;
                float v0 = acc[mi][ni][half * 2 + 0];
                float v1 = acc[mi][ni][half * 2 + 1];
                if (bias) { v0 += bias[c]; v1 += bias[c + 1]; }
                if (doGelu) { v0 = gelu_f(v0); v1 = gelu_f(v1); }
                v0 *= scl; v1 *= scl;
                float2* cp = (float2*)&Cp[(size_t)r * ldc + c];
                if (doAccum) {
                    float2 o = *cp;
                    v0 += o.x; v1 += o.y;
                }
                *cp = make_float2(v0, v1);
            }
        }
    }
}

// ---------------------------------------------------------------------------
// Attention over the W axis per (b,h) row (fp32, smem-resident)
// ---------------------------------------------------------------------------
__global__ __launch_bounds__(256) void attn_kernel(
    const float* __restrict__ qkv, float* __restrict__ obuf) {
    extern __shared__ float sm[];
    float* Qs = sm;
    float* Ks = sm + 96 * QKV_PAD;
    float* Vs = sm + 2 * 96 * QKV_PAD;
    float* Ss = sm + 3 * 96 * QKV_PAD;

    int bh = blockIdx.x;
    int b = bh / 96, h = bh % 96;
    int tid = threadIdx.x;
    const float* base = qkv + (size_t)bh * 96 * 384;

    for (int f = tid; f < 96 * 96; f += 256) {
        int p = f / 96;
        int q = f % 96;
        int c = q * 4;
        float4 v = *(const float4*)&base[(size_t)p * 384 + c];
        float* dst;
        if (c < 128)      dst = &Qs[p * QKV_PAD + c];
        else if (c < 256) dst = &Ks[p * QKV_PAD + c - 128];
        else              dst = &Vs[p * QKV_PAD + c - 256];
        *(float4*)dst = v;
    }
    __syncthreads();

    {
        int tx = tid & 15, ty = tid >> 4;
        int q0 = ty * 6, j0 = tx * 6;
        float acc[6][6] = {};
        for (int k = 0; k < 128; k += 4) {
            float4 qa[6];
#pragma unroll
            for (int i = 0; i < 6; i++)
                qa[i] = *(const float4*)&Qs[(q0 + i) * QKV_PAD + k];
#pragma unroll
            for (int j = 0; j < 6; j++) {
                float4 kv = *(const float4*)&Ks[(j0 + j) * QKV_PAD + k];
#pragma unroll
                for (int i = 0; i < 6; i++)
                    acc[i][j] += qa[i].x * kv.x + qa[i].y * kv.y +
                                 qa[i].z * kv.z + qa[i].w * kv.w;
            }
        }
#pragma unroll
        for (int i = 0; i < 6; i++)
#pragma unroll
            for (int j = 0; j < 6; j++)
                Ss[(q0 + i) * 96 + j0 + j] = acc[i][j] * ATTN_SCALE;
    }
    __syncthreads();

    {
        int wid = tid >> 5, lane = tid & 31;
        for (int r = wid; r < 96; r += 8) {
            float v0 = Ss[r * 96 + lane];
            float v1 = Ss[r * 96 + 32 + lane];
            float v2 = Ss[r * 96 + 64 + lane];
            float m = fmaxf(v0, fmaxf(v1, v2));
#pragma unroll
            for (int o = 16; o > 0; o >>= 1)
                m = fmaxf(m, __shfl_xor_sync(0xffffffffu, m, o));
            float e0 = expf(v0 - m), e1 = expf(v1 - m), e2 = expf(v2 - m);
            float s = e0 + e1 + e2;
#pragma unroll
            for (int o = 16; o > 0; o >>= 1)
                s += __shfl_xor_sync(0xffffffffu, s, o);
            float inv = 1.0f / s;
            Ss[r * 96 + lane] = e0 * inv;
            Ss[r * 96 + 32 + lane] = e1 * inv;
            Ss[r * 96 + 64 + lane] = e2 * inv;
        }
    }
    __syncthreads();

    {
        int tx = tid & 15, ty = tid >> 4;
        int c0 = tx * 8, q0 = ty * 6;
        float acc[6][8] = {};
        for (int k = 0; k < 96; k++) {
            float4 va = *(const float4*)&Vs[k * QKV_PAD + c0];
            float4 vb = *(const float4*)&Vs[k * QKV_PAD + c0 + 4];
#pragma unroll
            for (int i = 0; i < 6; i++) {
                float p = Ss[(q0 + i) * 96 + k];
                acc[i][0] += p * va.x; acc[i][1] += p * va.y;
                acc[i][2] += p * va.z; acc[i][3] += p * va.w;
                acc[i][4] += p * vb.x; acc[i][5] += p * vb.y;
                acc[i][6] += p * vb.z; acc[i][7] += p * vb.w;
            }
        }
#pragma unroll
        for (int i = 0; i < 6; i++) {
            int opix = (b * 96 + (q0 + i)) * 96 + h;
            float* dst = &obuf[(size_t)opix * HDIM + c0];
            *(float4*)dst = make_float4(acc[i][0], acc[i][1], acc[i][2], acc[i][3]);
            *(float4*)(dst + 4) = make_float4(acc[i][4], acc[i][5], acc[i][6], acc[i][7]);
        }
    }
}

// ---------------------------------------------------------------------------
// MoE top-2 gating
// ---------------------------------------------------------------------------
__global__ __launch_bounds__(256) void moe_gate_kernel(
    const float* __restrict__ xc, const float* __restrict__ wgf,
    float* __restrict__ mg) {
    int gid = blockIdx.x * blockDim.x + threadIdx.x;
    int pix = gid >> 5;
    int lane = gid & 31;
    if (pix >= NPIX) return;
    const float* xp = xc + (size_t)pix * CH;
    float l0 = 0.f, l1 = 0.f, l2 = 0.f;
#pragma unroll
    for (int i = 0; i < 12; i++) {
        int c = i * 32 + lane;
        float xv = xp[c];
        l0 += xv * wgf[c * 3 + 0];
        l1 += xv * wgf[c * 3 + 1];
        l2 += xv * wgf[c * 3 + 2];
    }
#pragma unroll
    for (int o = 16; o > 0; o >>= 1) {
        l0 += __shfl_xor_sync(0xffffffffu, l0, o);
        l1 += __shfl_xor_sync(0xffffffffu, l1, o);
        l2 += __shfl_xor_sync(0xffffffffu, l2, o);
    }
    if (lane == 0) {
        float l[3] = {l0, l1, l2};
        int i0 = 0;
        if (l[1] > l[i0]) i0 = 1;
        if (l[2] > l[i0]) i0 = 2;
        int i1 = -1;
        for (int j = 0; j < 3; j++)
            if (j != i0 && (i1 < 0 || l[j] > l[i1])) i1 = j;
        float e1 = expf(l[i1] - l[i0]);
        float inv = 1.0f / (1.0f + e1);
        float g[3] = {0.f, 0.f, 0.f};
        g[i0] = inv;
        g[i1] = e1 * inv;
        mg[pix * 3 + 0] = g[0];
        mg[pix * 3 + 1] = g[1];
        mg[pix * 3 + 2] = g[2];
    }
}

// ---------------------------------------------------------------------------
// Host launcher
// ---------------------------------------------------------------------------
extern "C" void kernel_launch(void* const* d_in, const int* in_sizes, int n_in,
                              void* d_out, int out_size) {
    (void)in_sizes; (void)n_in; (void)out_size;
    const float* x = (const float*)d_in[0];
    const float* w_conv[6] = {(const float*)d_in[1], (const float*)d_in[3],
                              (const float*)d_in[5], (const float*)d_in[7],
                              (const float*)d_in[9], (const float*)d_in[11]};
    const float* b_conv[6] = {(const float*)d_in[2], (const float*)d_in[4],
                              (const float*)d_in[6], (const float*)d_in[8],
                              (const float*)d_in[10], (const float*)d_in[12]};
    const float* wg1 = (const float*)d_in[13];
    const float* wg2 = (const float*)d_in[14];
    const float* wg3 = (const float*)d_in[15];
    const float* w_qkv = (const float*)d_in[16];
    const float* w_ap  = (const float*)d_in[17];
    const float* b_ap  = (const float*)d_in[18];
    const float* wgf   = (const float*)d_in[19];
    const float* w1    = (const float*)d_in[20];
    const float* b1    = (const float*)d_in[21];
    const float* w2    = (const float*)d_in[22];
    const float* b2    = (const float*)d_in[23];
    const float* wp    = (const float*)d_in[24];
    const float* bp    = (const float*)d_in[25];
    float* out = (float*)d_out;

    float *gates, *moe, *qkv, *obuf, *xc, *mgate, *hidden, *accum;
    cudaGetSymbolAddress((void**)&gates, g_gates);
    cudaGetSymbolAddress((void**)&moe, g_moe);
    cudaGetSymbolAddress((void**)&qkv, g_qkv);
    cudaGetSymbolAddress((void**)&obuf, g_obuf);
    cudaGetSymbolAddress((void**)&xc, g_xc);
    cudaGetSymbolAddress((void**)&mgate, g_mgate);
    cudaGetSymbolAddress((void**)&hidden, g_hidden);
    cudaGetSymbolAddress((void**)&accum, g_accum);

    cudaFuncSetAttribute(attn_kernel, cudaFuncAttributeMaxDynamicSharedMemorySize,
                         ATTN_SMEM_BYTES);
    cudaFuncSetAttribute(conv_moe_tc, cudaFuncAttributeMaxDynamicSharedMemorySize,
                         CONV_SMEM_BYTES);

    // 1. per-branch 2-way gates
    branch_gate_kernel<<<NPIX / 8, 256>>>(x, wg1, wg2, wg3, gates);

    // 2. branches
    for (int br = 0; br < 3; br++) {
        conv_moe_tc<<<dim3(3 * HGT, BATCH), 256, CONV_SMEM_BYTES>>>(
            x, w_conv[2 * br], b_conv[2 * br], w_conv[2 * br + 1],
            b_conv[2 * br + 1], gates, br, moe);
        gemm_tc<<<dim3((3 * HDIM) / 128, NPIX / 128), 256>>>(
            moe, HDIM, w_qkv + (size_t)br * HDIM * 3 * HDIM, 3 * HDIM,
            nullptr, nullptr, 0, 0, qkv, 3 * HDIM, HDIM, 0, 0);
        attn_kernel<<<BATCH * HGT, 256, ATTN_SMEM_BYTES>>>(qkv, obuf);
        gemm_tc<<<dim3(HDIM / 128, NPIX / 128), 256>>>(
            obuf, HDIM, w_ap + (size_t)br * HDIM * HDIM, HDIM,
            b_ap + (size_t)br * HDIM, nullptr, 0, 0,
            xc + br * HDIM, CH, HDIM, 0, 0);
    }

    // 3. top-2 MoE gates
    moe_gate_kernel<<<NPIX / 8, 256>>>(xc, wgf, mgate);

    // 4. dense 3-expert MLP with gated accumulation
    for (int e = 0; e < 3; e++) {
        gemm_tc<<<dim3(MLPH / 128, NPIX / 128), 256>>>(
            xc, CH, w1 + (size_t)e * CH * MLPH, MLPH, b1 + (size_t)e * MLPH,
            nullptr, 0, 0, hidden, MLPH, CH, 1, 0);
        gemm_tc<<<dim3(CH / 128, NPIX / 128), 256>>>(
            hidden, MLPH, w2 + (size_t)e * MLPH * CH, CH, b2 + (size_t)e * CH,
            mgate, 3, e, accum, CH, MLPH, 0, (e > 0) ? 1 : 0);
    }

    // 5. final projection
    gemm_tc<<<dim3(CH / 128, NPIX / 128), 256>>>(
        accum, CH, wp, CH, bp, nullptr, 0, 0, out, CH, CH, 0, 0);
}

// round 4
// speedup vs baseline: 3.0567x; 1.1014x over previous
#include <cuda_runtime.h>
#include <math.h>
#include <cstddef>

// ---------------------------------------------------------------------------
// Problem constants
// ---------------------------------------------------------------------------
namespace {
constexpr int BATCH = 4, HGT = 96, WID = 96, CH = 384, HDIM = 128;
constexpr int NPIX = BATCH * HGT * WID;   // 36864
constexpr int MLPH = 4 * CH;              // 1536
constexpr float ATTN_SCALE = 0.15430334996209191f; // (128//3)^-0.5
constexpr int ATTN_SMEM_BYTES = (3 * 96 * 132 + 96 * 100) * 4;   // 190464
constexpr int CONV_SMEM_BYTES = (2 * 32 * 132 + 2 * 64 * 132) * 4; // 101376
constexpr int GEMM_SMEM_BYTES = (2 * 128 * 36 + 2 * 32 * 132) * 4; // 70656
}

// ---------------------------------------------------------------------------
// Scratch (device globals)
// ---------------------------------------------------------------------------
__device__ float g_gates[NPIX * 6];
__device__ float g_moe[(size_t)NPIX * HDIM];
__device__ float g_qkv[(size_t)NPIX * 3 * HDIM];
__device__ float g_obuf[(size_t)NPIX * HDIM];
__device__ float g_xc[(size_t)NPIX * CH];
__device__ float g_mgate[NPIX * 3];
__device__ float g_hidden[(size_t)NPIX * MLPH];
__device__ float g_accum[(size_t)NPIX * CH];

__device__ __forceinline__ float gelu_f(float v) {
    float u = 0.7978845608028654f * (v + 0.044715f * v * v * v);
    return 0.5f * v * (1.0f + tanhf(u));
}

// m16n8k8 tf32 mma: D = A@B + D  (raw fp32 bit patterns; HW truncates to tf32)
__device__ __forceinline__ void mma8(float* c, const float* a, const float* b) {
    asm volatile(
        "mma.sync.aligned.m16n8k8.row.col.f32.tf32.tf32.f32 "
        "{%0,%1,%2,%3}, {%4,%5,%6,%7}, {%8,%9}, {%0,%1,%2,%3};"
        : "+f"(c[0]), "+f"(c[1]), "+f"(c[2]), "+f"(c[3])
        : "r"(__float_as_uint(a[0])), "r"(__float_as_uint(a[1])),
          "r"(__float_as_uint(a[2])), "r"(__float_as_uint(a[3])),
          "r"(__float_as_uint(b[0])), "r"(__float_as_uint(b[1])));
}

// cp.async helpers
__device__ __forceinline__ unsigned smem_u32p(const void* p) {
    return (unsigned)__cvta_generic_to_shared(p);
}
__device__ __forceinline__ void cp16(const void* dst, const void* src) {
    asm volatile("cp.async.cg.shared.global [%0],[%1],16;"
                 :: "r"(smem_u32p(dst)), "l"(src));
}
__device__ __forceinline__ void cp16z(const void* dst, const void* src, int sz) {
    asm volatile("cp.async.cg.shared.global [%0],[%1],16,%2;"
                 :: "r"(smem_u32p(dst)), "l"(src), "r"(sz));
}
__device__ __forceinline__ void cp_commit() {
    asm volatile("cp.async.commit_group;");
}
template <int N>
__device__ __forceinline__ void cp_wait() {
    asm volatile("cp.async.wait_group %0;" :: "n"(N));
}

// ---------------------------------------------------------------------------
// Branch gating (warp per pixel)
// ---------------------------------------------------------------------------
__device__ __forceinline__ void bg_dot(const float* xp, const float* wg, int lane,
                                       float& g0, float& g1) {
    float a0 = 0.f, a1 = 0.f;
#pragma unroll
    for (int i = 0; i < 4; i++) {
        int c = i * 32 + lane;
        float xv = xp[c];
        a0 += xv * wg[c * 2 + 0];
        a1 += xv * wg[c * 2 + 1];
    }
#pragma unroll
    for (int o = 16; o > 0; o >>= 1) {
        a0 += __shfl_xor_sync(0xffffffffu, a0, o);
        a1 += __shfl_xor_sync(0xffffffffu, a1, o);
    }
    float m = fmaxf(a0, a1);
    float e0 = expf(a0 - m), e1 = expf(a1 - m);
    float inv = 1.0f / (e0 + e1);
    g0 = e0 * inv;
    g1 = e1 * inv;
}

__global__ __launch_bounds__(256) void branch_gate_kernel(
    const float* __restrict__ x, const float* __restrict__ wg1,
    const float* __restrict__ wg2, const float* __restrict__ wg3,
    float* __restrict__ gates) {
    int gid = blockIdx.x * blockDim.x + threadIdx.x;
    int pix = gid >> 5;
    int lane = gid & 31;
    if (pix >= NPIX) return;
    const float* xp = x + (size_t)pix * CH;
    float g0, g1;
    bg_dot(xp + 0 * HDIM, wg1, lane, g0, g1);
    if (lane == 0) { gates[pix * 6 + 0] = g0; gates[pix * 6 + 1] = g1; }
    bg_dot(xp + 1 * HDIM, wg2, lane, g0, g1);
    if (lane == 0) { gates[pix * 6 + 2] = g0; gates[pix * 6 + 3] = g1; }
    bg_dot(xp + 2 * HDIM, wg3, lane, g0, g1);
    if (lane == 0) { gates[pix * 6 + 4] = g0; gates[pix * 6 + 5] = g1; }
}

// ---------------------------------------------------------------------------
// Fused dual-conv + gate, tensor cores, cp.async pipelined.
// Dual accumulators (convA / convB); gates applied in epilogue so the A tile
// is a pure async copy with zero-fill at the borders.
// 36 steps = 18 taps x 2 K-chunks of 64.
// ---------------------------------------------------------------------------
__global__ __launch_bounds__(256) void conv_moe_tc(
    const float* __restrict__ x,
    const float* __restrict__ wa, const float* __restrict__ ba,
    const float* __restrict__ wb, const float* __restrict__ bb,
    const float* __restrict__ gates, int br, float* __restrict__ moe) {
    extern __shared__ float cm[];
    float* sA = cm;                 // [2][32*132]
    float* sW = cm + 2 * 32 * 132;  // [2][64*132]
    __shared__ float sGA[32], sGB[32];

    int tid = threadIdx.x;
    int lane = tid & 31, wid = tid >> 5;
    int gid = lane >> 2, tig = lane & 3;
    int wn = wid * 16;

    int wc = blockIdx.x % 3;
    int h = blockIdx.x / 3;
    int b = blockIdx.y;
    int w0 = wc * 32;
    int pixbase = (b * HGT + h) * WID + w0;

    if (tid < 32) {
        sGA[tid] = gates[(size_t)(pixbase + tid) * 6 + br * 2 + 0];
        sGB[tid] = gates[(size_t)(pixbase + tid) * 6 + br * 2 + 1];
    }

    // tap -> (dh, dw)
    auto geo = [&](int t, int& dh, int& dw) {
        int tc = t % 9;
        int isB = (t >= 9);
        if (br == 0)      { dh = tc / 3 - 1; dw = tc % 3 - 1; }
        else if (br == 1) { dh = tc - 4;     dw = 0;          }
        else              { dh = 0;          dw = tc - 4;     }
        if (isB) { dh *= 2; dw *= 2; }
    };

    auto loadA = [&](int t, int buf) {
        int dh, dw;
        geo(t, dh, dw);
        int hh = h + dh;
        float* dstb = sA + buf * (32 * 132);
#pragma unroll
        for (int l = 0; l < 4; l++) {
            int f = tid + l * 256;
            int p = f >> 5;
            int ks = (f & 31) * 4;
            int wv = w0 + p + dw;
            bool ok = (hh >= 0 && hh < HGT && wv >= 0 && wv < WID);
            const float* src = ok
                ? &x[((size_t)((b * HGT + hh) * WID + wv)) * CH + br * HDIM + ks]
                : x;
            cp16z(dstb + p * 132 + ks, src, ok ? 16 : 0);
        }
    };

    auto loadW = [&](int s, int buf) {
        int t = s >> 1, chunk = s & 1;
        int tc = t % 9;
        const float* wt = ((t >= 9) ? wb : wa) + (size_t)tc * (HDIM * HDIM);
        float* dstb = sW + buf * (64 * 132);
#pragma unroll
        for (int l = 0; l < 8; l++) {
            int f = tid + l * 256;
            int k = f >> 5;
            int ns = (f & 31) * 4;
            cp16(dstb + k * 132 + ns, &wt[(size_t)(chunk * 64 + k) * HDIM + ns]);
        }
    };

    loadA(0, 0);
    loadW(0, 0);
    cp_commit();

    float accA[2][2][4] = {};
    float accB[2][2][4] = {};

    for (int s = 0; s < 36; s++) {
        int tap = s >> 1;
        if (s + 1 < 36) loadW(s + 1, (s + 1) & 1);
        if ((s & 1) == 0 && tap + 1 < 18) loadA(tap + 1, (tap + 1) & 1);
        cp_commit();
        cp_wait<1>();
        __syncthreads();

        const float* Ac = sA + (tap & 1) * (32 * 132);
        const float* Wc = sW + (s & 1) * (64 * 132);
        int kgb = (s & 1) * 64;
        float (*acc)[2][4] = (tap < 9) ? accA : accB;

#pragma unroll
        for (int kk = 0; kk < 64; kk += 8) {
            int kg = kgb + kk;
            float a[2][4], bf[2][2];
#pragma unroll
            for (int mi = 0; mi < 2; mi++) {
                int r = mi * 16 + gid;
                a[mi][0] = Ac[r * 132 + kg + tig];
                a[mi][1] = Ac[(r + 8) * 132 + kg + tig];
                a[mi][2] = Ac[r * 132 + kg + tig + 4];
                a[mi][3] = Ac[(r + 8) * 132 + kg + tig + 4];
            }
#pragma unroll
            for (int ni = 0; ni < 2; ni++) {
                int c = wn + ni * 8 + gid;
                bf[ni][0] = Wc[(kk + tig) * 132 + c];
                bf[ni][1] = Wc[(kk + tig + 4) * 132 + c];
            }
#pragma unroll
            for (int mi = 0; mi < 2; mi++)
#pragma unroll
                for (int ni = 0; ni < 2; ni++)
                    mma8(acc[mi][ni], a[mi], bf[ni]);
        }
        __syncthreads();
    }

    // epilogue: moe = gA*(accA+ba) + gB*(accB+bb)
#pragma unroll
    for (int mi = 0; mi < 2; mi++) {
#pragma unroll
        for (int half = 0; half < 2; half++) {
            int p = mi * 16 + gid + half * 8;
            float gg0 = sGA[p], gg1 = sGB[p];
#pragma unroll
            for (int ni = 0; ni < 2; ni++) {
                int c = wn + ni * 8 + tig * 2;
                float v0 = gg0 * (accA[mi][ni][half * 2 + 0] + ba[c]) +
                           gg1 * (accB[mi][ni][half * 2 + 0] + bb[c]);
                float v1 = gg0 * (accA[mi][ni][half * 2 + 1] + ba[c + 1]) +
                           gg1 * (accB[mi][ni][half * 2 + 1] + bb[c + 1]);
                *(float2*)&moe[(size_t)(pixbase + p) * HDIM + c] = make_float2(v0, v1);
            }
        }
    }
}

// ---------------------------------------------------------------------------
// Tensor-core GEMM, cp.async 2-stage pipeline, raw fp32 -> tf32 truncation.
// BM=BN=128, BK=32, 256 threads, warp grid 2x4 (warp tile 64x32).
// ---------------------------------------------------------------------------
__global__ __launch_bounds__(256, 2) void gemm_tc(
    const float* __restrict__ A, int lda,
    const float* __restrict__ B, int ldb,
    const float* __restrict__ bias,
    const float* __restrict__ rowscale, int rs_stride, int rs_off,
    float* __restrict__ Cp, int ldc, int K, int doGelu, int doAccum) {
    extern __shared__ float gsm[];
    float* sA = gsm;                  // [2][128*36]
    float* sB = gsm + 2 * 128 * 36;   // [2][32*132]

    int tid = threadIdx.x;
    int lane = tid & 31, wid = tid >> 5;
    int gid = lane >> 2, tig = lane & 3;
    int wm = (wid >> 2) * 64, wn = (wid & 3) * 32;
    int m0 = blockIdx.y * 128, n0 = blockIdx.x * 128;

    auto loadA = [&](int k0, float* dst) {
#pragma unroll
        for (int l = 0; l < 4; l++) {
            int f = tid + l * 256;
            int m = f >> 3;
            int ks = (f & 7) * 4;
            cp16(dst + m * 36 + ks, &A[(size_t)(m0 + m) * lda + k0 + ks]);
        }
    };
    auto loadB = [&](int k0, float* dst) {
#pragma unroll
        for (int l = 0; l < 4; l++) {
            int f = tid + l * 256;
            int k = f >> 5;
            int ns = (f & 31) * 4;
            cp16(dst + k * 132 + ns, &B[(size_t)(k0 + k) * ldb + n0 + ns]);
        }
    };

    int nk = K / 32;
    loadA(0, sA);
    loadB(0, sB);
    cp_commit();

    float acc[4][4][4] = {};

    for (int i = 0; i < nk; i++) {
        if (i + 1 < nk) {
            loadA((i + 1) * 32, sA + ((i + 1) & 1) * (128 * 36));
            loadB((i + 1) * 32, sB + ((i + 1) & 1) * (32 * 132));
        }
        cp_commit();
        cp_wait<1>();
        __syncthreads();

        const float* Ac = sA + (i & 1) * (128 * 36);
        const float* Bc = sB + (i & 1) * (32 * 132);
#pragma unroll
        for (int kk = 0; kk < 32; kk += 8) {
            float a[4][4], bf[4][2];
#pragma unroll
            for (int mi = 0; mi < 4; mi++) {
                int r = wm + mi * 16 + gid;
                a[mi][0] = Ac[r * 36 + kk + tig];
                a[mi][1] = Ac[(r + 8) * 36 + kk + tig];
                a[mi][2] = Ac[r * 36 + kk + tig + 4];
                a[mi][3] = Ac[(r + 8) * 36 + kk + tig + 4];
            }
#pragma unroll
            for (int ni = 0; ni < 4; ni++) {
                int c = wn + ni * 8 + gid;
                bf[ni][0] = Bc[(kk + tig) * 132 + c];
                bf[ni][1] = Bc[(kk + tig + 4) * 132 + c];
            }
#pragma unroll
            for (int mi = 0; mi < 4; mi++)
#pragma unroll
                for (int ni = 0; ni < 4; ni++)
                    mma8(acc[mi][ni], a[mi], bf[ni]);
        }
        __syncthreads();
    }

    // epilogue
#pragma unroll
    for (int mi = 0; mi < 4; mi++) {
#pragma unroll
        for (int half = 0; half < 2; half++) {
            int r = m0 + wm + mi * 16 + gid + half * 8;
            float scl = rowscale ? rowscale[(size_t)r * rs_stride + rs_off] : 1.0f;
#pragma unroll
            for (int ni = 0; ni < 4; ni++) {
                int c = n0 + wn + ni * 8 + tig * 2;
                float v0 = acc[mi][ni][half * 2 + 0];
                float v1 = acc[mi][ni][half * 2 + 1];
                if (bias) { v0 += bias[c]; v1 += bias[c + 1]; }
                if (doGelu) { v0 = gelu_f(v0); v1 = gelu_f(v1); }
                v0 *= scl; v1 *= scl;
                float2* cp = (float2*)&Cp[(size_t)r * ldc + c];
                if (doAccum) {
                    float2 o = *cp;
                    v0 += o.x; v1 += o.y;
                }
                *cp = make_float2(v0, v1);
            }
        }
    }
}

// ---------------------------------------------------------------------------
// Attention over the W axis per (b,h) row — tensor-core QK^T and SV phases.
// Q scaled by ATTN_SCALE at load. S stored at stride 100 (conflict-free
// fragment reads: gid*4+tig spans all 32 banks).
// ---------------------------------------------------------------------------
__global__ __launch_bounds__(256) void attn_tc(
    const float* __restrict__ qkv, float* __restrict__ obuf) {
    extern __shared__ float sm[];
    float* Qs = sm;                    // [96][132]
    float* Ks = sm + 96 * 132;
    float* Vs = sm + 2 * 96 * 132;
    float* Ss = sm + 3 * 96 * 132;     // [96][100]

    int bh = blockIdx.x;
    int b = bh / 96, h = bh % 96;
    int tid = threadIdx.x;
    int lane = tid & 31, wid = tid >> 5;
    int gid = lane >> 2, tig = lane & 3;
    const float* base = qkv + (size_t)bh * 96 * 384;

    for (int f = tid; f < 96 * 96; f += 256) {
        int p = f / 96;
        int q = f % 96;
        int c = q * 4;
        float4 v = *(const float4*)&base[(size_t)p * 384 + c];
        if (c < 128) {
            v.x *= ATTN_SCALE; v.y *= ATTN_SCALE;
            v.z *= ATTN_SCALE; v.w *= ATTN_SCALE;
            *(float4*)&Qs[p * 132 + c] = v;
        } else if (c < 256) {
            *(float4*)&Ks[p * 132 + c - 128] = v;
        } else {
            *(float4*)&Vs[p * 132 + c - 256] = v;
        }
    }
    __syncthreads();

    // phase 1: S = (scaled Q) @ K^T  — m=96, n=96, k=128
    {
        int wm = (wid >> 2) * 48, wn = (wid & 3) * 24;
        float acc[3][3][4] = {};
#pragma unroll
        for (int kk = 0; kk < 128; kk += 8) {
            float a[3][4], bf[3][2];
#pragma unroll
            for (int mi = 0; mi < 3; mi++) {
                int r = wm + mi * 16 + gid;
                a[mi][0] = Qs[r * 132 + kk + tig];
                a[mi][1] = Qs[(r + 8) * 132 + kk + tig];
                a[mi][2] = Qs[r * 132 + kk + tig + 4];
                a[mi][3] = Qs[(r + 8) * 132 + kk + tig + 4];
            }
#pragma unroll
            for (int ni = 0; ni < 3; ni++) {
                int c = wn + ni * 8 + gid;
                bf[ni][0] = Ks[c * 132 + kk + tig];
                bf[ni][1] = Ks[c * 132 + kk + tig + 4];
            }
#pragma unroll
            for (int mi = 0; mi < 3; mi++)
#pragma unroll
                for (int ni = 0; ni < 3; ni++)
                    mma8(acc[mi][ni], a[mi], bf[ni]);
        }
#pragma unroll
        for (int mi = 0; mi < 3; mi++)
#pragma unroll
            for (int half = 0; half < 2; half++) {
                int r = wm + mi * 16 + gid + half * 8;
#pragma unroll
                for (int ni = 0; ni < 3; ni++) {
                    int c = wn + ni * 8 + tig * 2;
                    Ss[r * 100 + c] = acc[mi][ni][half * 2 + 0];
                    Ss[r * 100 + c + 1] = acc[mi][ni][half * 2 + 1];
                }
            }
    }
    __syncthreads();

    // phase 2: row softmax (warp per row)
    {
        int w8 = tid >> 5, ln = tid & 31;
        for (int r = w8; r < 96; r += 8) {
            float v0 = Ss[r * 100 + ln];
            float v1 = Ss[r * 100 + 32 + ln];
            float v2 = Ss[r * 100 + 64 + ln];
            float m = fmaxf(v0, fmaxf(v1, v2));
#pragma unroll
            for (int o = 16; o > 0; o >>= 1)
                m = fmaxf(m, __shfl_xor_sync(0xffffffffu, m, o));
            float e0 = expf(v0 - m), e1 = expf(v1 - m), e2 = expf(v2 - m);
            float s = e0 + e1 + e2;
#pragma unroll
            for (int o = 16; o > 0; o >>= 1)
                s += __shfl_xor_sync(0xffffffffu, s, o);
            float inv = 1.0f / s;
            Ss[r * 100 + ln] = e0 * inv;
            Ss[r * 100 + 32 + ln] = e1 * inv;
            Ss[r * 100 + 64 + ln] = e2 * inv;
        }
    }
    __syncthreads();

    // phase 3: O = S @ V — m=96, n=128, k=96; transposed store to obuf
    {
        int wm = (wid >> 2) * 48, wn = (wid & 3) * 32;
        float acc[3][4][4] = {};
#pragma unroll
        for (int kk = 0; kk < 96; kk += 8) {
            float a[3][4], bf[4][2];
#pragma unroll
            for (int mi = 0; mi < 3; mi++) {
                int r = wm + mi * 16 + gid;
                a[mi][0] = Ss[r * 100 + kk + tig];
                a[mi][1] = Ss[(r + 8) * 100 + kk + tig];
                a[mi][2] = Ss[r * 100 + kk + tig + 4];
                a[mi][3] = Ss[(r + 8) * 100 + kk + tig + 4];
            }
#pragma unroll
            for (int ni = 0; ni < 4; ni++) {
                int c = wn + ni * 8 + gid;
                bf[ni][0] = Vs[(kk + tig) * 132 + c];
                bf[ni][1] = Vs[(kk + tig + 4) * 132 + c];
            }
#pragma unroll
            for (int mi = 0; mi < 3; mi++)
#pragma unroll
                for (int ni = 0; ni < 4; ni++)
                    mma8(acc[mi][ni], a[mi], bf[ni]);
        }
#pragma unroll
        for (int mi = 0; mi < 3; mi++)
#pragma unroll
            for (int half = 0; half < 2; half++) {
                int q = wm + mi * 16 + gid + half * 8;
                int opix = (b * 96 + q) * 96 + h;
#pragma unroll
                for (int ni = 0; ni < 4; ni++) {
                    int c = wn + ni * 8 + tig * 2;
                    *(float2*)&obuf[(size_t)opix * HDIM + c] =
                        make_float2(acc[mi][ni][half * 2 + 0],
                                    acc[mi][ni][half * 2 + 1]);
                }
            }
    }
}

// ---------------------------------------------------------------------------
// MoE top-2 gating
// ---------------------------------------------------------------------------
__global__ __launch_bounds__(256) void moe_gate_kernel(
    const float* __restrict__ xc, const float* __restrict__ wgf,
    float* __restrict__ mg) {
    int gid = blockIdx.x * blockDim.x + threadIdx.x;
    int pix = gid >> 5;
    int lane = gid & 31;
    if (pix >= NPIX) return;
    const float* xp = xc + (size_t)pix * CH;
    float l0 = 0.f, l1 = 0.f, l2 = 0.f;
#pragma unroll
    for (int i = 0; i < 12; i++) {
        int c = i * 32 + lane;
        float xv = xp[c];
        l0 += xv * wgf[c * 3 + 0];
        l1 += xv * wgf[c * 3 + 1];
        l2 += xv * wgf[c * 3 + 2];
    }
#pragma unroll
    for (int o = 16; o > 0; o >>= 1) {
        l0 += __shfl_xor_sync(0xffffffffu, l0, o);
        l1 += __shfl_xor_sync(0xffffffffu, l1, o);
        l2 += __shfl_xor_sync(0xffffffffu, l2, o);
    }
    if (lane == 0) {
        float l[3] = {l0, l1, l2};
        int i0 = 0;
        if (l[1] > l[i0]) i0 = 1;
        if (l[2] > l[i0]) i0 = 2;
        int i1 = -1;
        for (int j = 0; j < 3; j++)
            if (j != i0 && (i1 < 0 || l[j] > l[i1])) i1 = j;
        float e1 = expf(l[i1] - l[i0]);
        float inv = 1.0f / (1.0f + e1);
        float g[3] = {0.f, 0.f, 0.f};
        g[i0] = inv;
        g[i1] = e1 * inv;
        mg[pix * 3 + 0] = g[0];
        mg[pix * 3 + 1] = g[1];
        mg[pix * 3 + 2] = g[2];
    }
}

// ---------------------------------------------------------------------------
// Host launcher
// ---------------------------------------------------------------------------
extern "C" void kernel_launch(void* const* d_in, const int* in_sizes, int n_in,
                              void* d_out, int out_size) {
    (void)in_sizes; (void)n_in; (void)out_size;
    const float* x = (const float*)d_in[0];
    const float* w_conv[6] = {(const float*)d_in[1], (const float*)d_in[3],
                              (const float*)d_in[5], (const float*)d_in[7],
                              (const float*)d_in[9], (const float*)d_in[11]};
    const float* b_conv[6] = {(const float*)d_in[2], (const float*)d_in[4],
                              (const float*)d_in[6], (const float*)d_in[8],
                              (const float*)d_in[10], (const float*)d_in[12]};
    const float* wg1 = (const float*)d_in[13];
    const float* wg2 = (const float*)d_in[14];
    const float* wg3 = (const float*)d_in[15];
    const float* w_qkv = (const float*)d_in[16];
    const float* w_ap  = (const float*)d_in[17];
    const float* b_ap  = (const float*)d_in[18];
    const float* wgf   = (const float*)d_in[19];
    const float* w1    = (const float*)d_in[20];
    const float* b1    = (const float*)d_in[21];
    const float* w2    = (const float*)d_in[22];
    const float* b2    = (const float*)d_in[23];
    const float* wp    = (const float*)d_in[24];
    const float* bp    = (const float*)d_in[25];
    float* out = (float*)d_out;

    float *gates, *moe, *qkv, *obuf, *xc, *mgate, *hidden, *accum;
    cudaGetSymbolAddress((void**)&gates, g_gates);
    cudaGetSymbolAddress((void**)&moe, g_moe);
    cudaGetSymbolAddress((void**)&qkv, g_qkv);
    cudaGetSymbolAddress((void**)&obuf, g_obuf);
    cudaGetSymbolAddress((void**)&xc, g_xc);
    cudaGetSymbolAddress((void**)&mgate, g_mgate);
    cudaGetSymbolAddress((void**)&hidden, g_hidden);
    cudaGetSymbolAddress((void**)&accum, g_accum);

    cudaFuncSetAttribute(attn_tc, cudaFuncAttributeMaxDynamicSharedMemorySize,
                         ATTN_SMEM_BYTES);
    cudaFuncSetAttribute(conv_moe_tc, cudaFuncAttributeMaxDynamicSharedMemorySize,
                         CONV_SMEM_BYTES);
    cudaFuncSetAttribute(gemm_tc, cudaFuncAttributeMaxDynamicSharedMemorySize,
                         GEMM_SMEM_BYTES);

    // 1. per-branch 2-way gates
    branch_gate_kernel<<<NPIX / 8, 256>>>(x, wg1, wg2, wg3, gates);

    // 2. branches
    for (int br = 0; br < 3; br++) {
        conv_moe_tc<<<dim3(3 * HGT, BATCH), 256, CONV_SMEM_BYTES>>>(
            x, w_conv[2 * br], b_conv[2 * br], w_conv[2 * br + 1],
            b_conv[2 * br + 1], gates, br, moe);
        gemm_tc<<<dim3((3 * HDIM) / 128, NPIX / 128), 256, GEMM_SMEM_BYTES>>>(
            moe, HDIM, w_qkv + (size_t)br * HDIM * 3 * HDIM, 3 * HDIM,
            nullptr, nullptr, 0, 0, qkv, 3 * HDIM, HDIM, 0, 0);
        attn_tc<<<BATCH * HGT, 256, ATTN_SMEM_BYTES>>>(qkv, obuf);
        gemm_tc<<<dim3(HDIM / 128, NPIX / 128), 256, GEMM_SMEM_BYTES>>>(
            obuf, HDIM, w_ap + (size_t)br * HDIM * HDIM, HDIM,
            b_ap + (size_t)br * HDIM, nullptr, 0, 0,
            xc + br * HDIM, CH, HDIM, 0, 0);
    }

    // 3. top-2 MoE gates
    moe_gate_kernel<<<NPIX / 8, 256>>>(xc, wgf, mgate);

    // 4. dense 3-expert MLP with gated accumulation
    for (int e = 0; e < 3; e++) {
        gemm_tc<<<dim3(MLPH / 128, NPIX / 128), 256, GEMM_SMEM_BYTES>>>(
            xc, CH, w1 + (size_t)e * CH * MLPH, MLPH, b1 + (size_t)e * MLPH,
            nullptr, 0, 0, hidden, MLPH, CH, 1, 0);
        gemm_tc<<<dim3(CH / 128, NPIX / 128), 256, GEMM_SMEM_BYTES>>>(
            hidden, MLPH, w2 + (size_t)e * MLPH * CH, CH, b2 + (size_t)e * CH,
            mgate, 3, e, accum, CH, MLPH, 0, (e > 0) ? 1 : 0);
    }

    // 5. final projection
    gemm_tc<<<dim3(CH / 128, NPIX / 128), 256, GEMM_SMEM_BYTES>>>(
        accum, CH, wp, CH, bp, nullptr, 0, 0, out, CH, CH, 0, 0);
}

// round 6
// speedup vs baseline: 3.6753x; 1.2024x over previous
#include <cuda_runtime.h>
#include <math.h>
#include <cstddef>

// ---------------------------------------------------------------------------
// Problem constants
// ---------------------------------------------------------------------------
namespace {
constexpr int BATCH = 4, HGT = 96, WID = 96, CH = 384, HDIM = 128;
constexpr int NPIX = BATCH * HGT * WID;   // 36864
constexpr int NPAD = NPIX + 128;
constexpr int MLPH = 4 * CH;              // 1536
constexpr float ATTN_SCALE = 0.15430334996209191f; // (128//3)^-0.5
constexpr int ATTN_SMEM_BYTES = (3 * 96 * 132 + 96 * 100) * 4;     // 190464
constexpr int CONV_SMEM_BYTES = (2 * 32 * 132 + 2 * 64 * 132) * 4; // 101376
constexpr int GEMM_SMEM_BYTES = (2 * 128 * 36 + 2 * 32 * 132) * 4; // 70656
}

// ---------------------------------------------------------------------------
// Scratch (device globals)
// ---------------------------------------------------------------------------
__device__ float g_gates[NPIX * 6];
__device__ float g_moe[(size_t)NPIX * HDIM];
__device__ float g_qkv[(size_t)NPIX * 3 * HDIM];
__device__ float g_obuf[(size_t)NPIX * HDIM];
__device__ float g_xc[(size_t)NPAD * CH];
__device__ float g_mgate[NPAD * 3];
__device__ float g_hidden[(size_t)NPAD * MLPH];
__device__ float g_accum[(size_t)NPAD * CH];
__device__ int g_midx[3 * NPAD];
__device__ int g_cnt[3];
__device__ int g_cntp[3];

__device__ __forceinline__ float gelu_f(float v) {
    float u = 0.7978845608028654f * (v + 0.044715f * v * v * v);
    return 0.5f * v * (1.0f + tanhf(u));
}

// m16n8k8 tf32 mma: D = A@B + D  (raw fp32 bit patterns; HW truncates to tf32)
__device__ __forceinline__ void mma8(float* c, const float* a, const float* b) {
    asm volatile(
        "mma.sync.aligned.m16n8k8.row.col.f32.tf32.tf32.f32 "
        "{%0,%1,%2,%3}, {%4,%5,%6,%7}, {%8,%9}, {%0,%1,%2,%3};"
        : "+f"(c[0]), "+f"(c[1]), "+f"(c[2]), "+f"(c[3])
        : "r"(__float_as_uint(a[0])), "r"(__float_as_uint(a[1])),
          "r"(__float_as_uint(a[2])), "r"(__float_as_uint(a[3])),
          "r"(__float_as_uint(b[0])), "r"(__float_as_uint(b[1])));
}

// cp.async helpers
__device__ __forceinline__ unsigned smem_u32p(const void* p) {
    return (unsigned)__cvta_generic_to_shared(p);
}
__device__ __forceinline__ void cp16(const void* dst, const void* src) {
    asm volatile("cp.async.cg.shared.global [%0],[%1],16;"
                 :: "r"(smem_u32p(dst)), "l"(src));
}
__device__ __forceinline__ void cp16z(const void* dst, const void* src, int sz) {
    asm volatile("cp.async.cg.shared.global [%0],[%1],16,%2;"
                 :: "r"(smem_u32p(dst)), "l"(src), "r"(sz));
}
__device__ __forceinline__ void cp_commit() {
    asm volatile("cp.async.commit_group;");
}
template <int N>
__device__ __forceinline__ void cp_wait() {
    asm volatile("cp.async.wait_group %0;" :: "n"(N));
}

// ---------------------------------------------------------------------------
// Branch gating (warp per pixel)
// ---------------------------------------------------------------------------
__device__ __forceinline__ void bg_dot(const float* xp, const float* wg, int lane,
                                       float& g0, float& g1) {
    float a0 = 0.f, a1 = 0.f;
#pragma unroll
    for (int i = 0; i < 4; i++) {
        int c = i * 32 + lane;
        float xv = xp[c];
        a0 += xv * wg[c * 2 + 0];
        a1 += xv * wg[c * 2 + 1];
    }
#pragma unroll
    for (int o = 16; o > 0; o >>= 1) {
        a0 += __shfl_xor_sync(0xffffffffu, a0, o);
        a1 += __shfl_xor_sync(0xffffffffu, a1, o);
    }
    float m = fmaxf(a0, a1);
    float e0 = expf(a0 - m), e1 = expf(a1 - m);
    float inv = 1.0f / (e0 + e1);
    g0 = e0 * inv;
    g1 = e1 * inv;
}

__global__ __launch_bounds__(256) void branch_gate_kernel(
    const float* __restrict__ x, const float* __restrict__ wg1,
    const float* __restrict__ wg2, const float* __restrict__ wg3,
    float* __restrict__ gates) {
    int gid = blockIdx.x * blockDim.x + threadIdx.x;
    int pix = gid >> 5;
    int lane = gid & 31;
    if (pix >= NPIX) return;
    const float* xp = x + (size_t)pix * CH;
    float g0, g1;
    bg_dot(xp + 0 * HDIM, wg1, lane, g0, g1);
    if (lane == 0) { gates[pix * 6 + 0] = g0; gates[pix * 6 + 1] = g1; }
    bg_dot(xp + 1 * HDIM, wg2, lane, g0, g1);
    if (lane == 0) { gates[pix * 6 + 2] = g0; gates[pix * 6 + 3] = g1; }
    bg_dot(xp + 2 * HDIM, wg3, lane, g0, g1);
    if (lane == 0) { gates[pix * 6 + 4] = g0; gates[pix * 6 + 5] = g1; }
}

// ---------------------------------------------------------------------------
// Fused dual-conv + gate (mma.sync, cp.async pipelined)
// ---------------------------------------------------------------------------
__global__ __launch_bounds__(256) void conv_moe_tc(
    const float* __restrict__ x,
    const float* __restrict__ wa, const float* __restrict__ ba,
    const float* __restrict__ wb, const float* __restrict__ bb,
    const float* __restrict__ gates, int br, float* __restrict__ moe) {
    extern __shared__ float cm[];
    float* sA = cm;                 // [2][32*132]
    float* sW = cm + 2 * 32 * 132;  // [2][64*132]
    __shared__ float sGA[32], sGB[32];

    int tid = threadIdx.x;
    int lane = tid & 31, wid = tid >> 5;
    int gid = lane >> 2, tig = lane & 3;
    int wn = wid * 16;

    int wc = blockIdx.x % 3;
    int h = blockIdx.x / 3;
    int b = blockIdx.y;
    int w0 = wc * 32;
    int pixbase = (b * HGT + h) * WID + w0;

    if (tid < 32) {
        sGA[tid] = gates[(size_t)(pixbase + tid) * 6 + br * 2 + 0];
        sGB[tid] = gates[(size_t)(pixbase + tid) * 6 + br * 2 + 1];
    }

    auto geo = [&](int t, int& dh, int& dw) {
        int tc = t % 9;
        int isB = (t >= 9);
        if (br == 0)      { dh = tc / 3 - 1; dw = tc % 3 - 1; }
        else if (br == 1) { dh = tc - 4;     dw = 0;          }
        else              { dh = 0;          dw = tc - 4;     }
        if (isB) { dh *= 2; dw *= 2; }
    };

    auto loadA = [&](int t, int buf) {
        int dh, dw;
        geo(t, dh, dw);
        int hh = h + dh;
        float* dstb = sA + buf * (32 * 132);
#pragma unroll
        for (int l = 0; l < 4; l++) {
            int f = tid + l * 256;
            int p = f >> 5;
            int ks = (f & 31) * 4;
            int wv = w0 + p + dw;
            bool ok = (hh >= 0 && hh < HGT && wv >= 0 && wv < WID);
            const float* src = ok
                ? &x[((size_t)((b * HGT + hh) * WID + wv)) * CH + br * HDIM + ks]
                : x;
            cp16z(dstb + p * 132 + ks, src, ok ? 16 : 0);
        }
    };

    auto loadW = [&](int s, int buf) {
        int t = s >> 1, chunk = s & 1;
        int tc = t % 9;
        const float* wt = ((t >= 9) ? wb : wa) + (size_t)tc * (HDIM * HDIM);
        float* dstb = sW + buf * (64 * 132);
#pragma unroll
        for (int l = 0; l < 8; l++) {
            int f = tid + l * 256;
            int k = f >> 5;
            int ns = (f & 31) * 4;
            cp16(dstb + k * 132 + ns, &wt[(size_t)(chunk * 64 + k) * HDIM + ns]);
        }
    };

    loadA(0, 0);
    loadW(0, 0);
    cp_commit();

    float accA[2][2][4] = {};
    float accB[2][2][4] = {};

    for (int s = 0; s < 36; s++) {
        int tap = s >> 1;
        if (s + 1 < 36) loadW(s + 1, (s + 1) & 1);
        if ((s & 1) == 0 && tap + 1 < 18) loadA(tap + 1, (tap + 1) & 1);
        cp_commit();
        cp_wait<1>();
        __syncthreads();

        const float* Ac = sA + (tap & 1) * (32 * 132);
        const float* Wc = sW + (s & 1) * (64 * 132);
        int kgb = (s & 1) * 64;
        float (*acc)[2][4] = (tap < 9) ? accA : accB;

#pragma unroll
        for (int kk = 0; kk < 64; kk += 8) {
            int kg = kgb + kk;
            float a[2][4], bf[2][2];
#pragma unroll
            for (int mi = 0; mi < 2; mi++) {
                int r = mi * 16 + gid;
                a[mi][0] = Ac[r * 132 + kg + tig];
                a[mi][1] = Ac[(r + 8) * 132 + kg + tig];
                a[mi][2] = Ac[r * 132 + kg + tig + 4];
                a[mi][3] = Ac[(r + 8) * 132 + kg + tig + 4];
            }
#pragma unroll
            for (int ni = 0; ni < 2; ni++) {
                int c = wn + ni * 8 + gid;
                bf[ni][0] = Wc[(kk + tig) * 132 + c];
                bf[ni][1] = Wc[(kk + tig + 4) * 132 + c];
            }
#pragma unroll
            for (int mi = 0; mi < 2; mi++)
#pragma unroll
                for (int ni = 0; ni < 2; ni++)
                    mma8(acc[mi][ni], a[mi], bf[ni]);
        }
        __syncthreads();
    }

#pragma unroll
    for (int mi = 0; mi < 2; mi++) {
#pragma unroll
        for (int half = 0; half < 2; half++) {
            int p = mi * 16 + gid + half * 8;
            float gg0 = sGA[p], gg1 = sGB[p];
#pragma unroll
            for (int ni = 0; ni < 2; ni++) {
                int c = wn + ni * 8 + tig * 2;
                float v0 = gg0 * (accA[mi][ni][half * 2 + 0] + ba[c]) +
                           gg1 * (accB[mi][ni][half * 2 + 0] + bb[c]);
                float v1 = gg0 * (accA[mi][ni][half * 2 + 1] + ba[c + 1]) +
                           gg1 * (accB[mi][ni][half * 2 + 1] + bb[c + 1]);
                *(float2*)&moe[(size_t)(pixbase + p) * HDIM + c] = make_float2(v0, v1);
            }
        }
    }
}

// ---------------------------------------------------------------------------
// Tensor-core GEMM, cp.async 2-stage pipeline, tf32, with optional
// gather (A rows) or scatter (C rows) through an index list + row count.
// map==null: dense. mapA=1: A row = map[m], C row = m (MLP1 gather).
// mapA=0: A row = m, C row = map[m], rowscale keyed on map[m] (MLP2 scatter).
// ---------------------------------------------------------------------------
__global__ __launch_bounds__(256, 2) void gemm_tc(
    const float* __restrict__ A, int lda,
    const float* __restrict__ B, int ldb,
    const float* __restrict__ bias,
    const float* __restrict__ rowscale, int rs_stride, int rs_off,
    float* __restrict__ Cp, int ldc, int K, int doGelu, int doAccum,
    const int* __restrict__ map, int mapA, const int* __restrict__ cntp) {
    extern __shared__ float gsm[];
    float* sA = gsm;                  // [2][128*36]
    float* sB = gsm + 2 * 128 * 36;   // [2][32*132]
    __shared__ int sMap[128];

    int tid = threadIdx.x;
    int m0 = blockIdx.y * 128, n0 = blockIdx.x * 128;
    if (cntp && m0 >= *cntp) return;

    int lane = tid & 31, wid = tid >> 5;
    int gid = lane >> 2, tig = lane & 3;
    int wm = (wid >> 2) * 64, wn = (wid & 3) * 32;

    if (map) {
        if (tid < 128) sMap[tid] = map[m0 + tid];
        __syncthreads();
    }

    auto loadA = [&](int k0, float* dst) {
#pragma unroll
        for (int l = 0; l < 4; l++) {
            int f = tid + l * 256;
            int m = f >> 3;
            int ks = (f & 7) * 4;
            int ar = (map && mapA) ? sMap[m] : (m0 + m);
            cp16(dst + m * 36 + ks, &A[(size_t)ar * lda + k0 + ks]);
        }
    };
    auto loadB = [&](int k0, float* dst) {
#pragma unroll
        for (int l = 0; l < 4; l++) {
            int f = tid + l * 256;
            int k = f >> 5;
            int ns = (f & 31) * 4;
            cp16(dst + k * 132 + ns, &B[(size_t)(k0 + k) * ldb + n0 + ns]);
        }
    };

    int nk = K / 32;
    loadA(0, sA);
    loadB(0, sB);
    cp_commit();

    float acc[4][4][4] = {};

    for (int i = 0; i < nk; i++) {
        if (i + 1 < nk) {
            loadA((i + 1) * 32, sA + ((i + 1) & 1) * (128 * 36));
            loadB((i + 1) * 32, sB + ((i + 1) & 1) * (32 * 132));
        }
        cp_commit();
        cp_wait<1>();
        __syncthreads();

        const float* Ac = sA + (i & 1) * (128 * 36);
        const float* Bc = sB + (i & 1) * (32 * 132);
#pragma unroll
        for (int kk = 0; kk < 32; kk += 8) {
            float a[4][4], bf[4][2];
#pragma unroll
            for (int mi = 0; mi < 4; mi++) {
                int r = wm + mi * 16 + gid;
                a[mi][0] = Ac[r * 36 + kk + tig];
                a[mi][1] = Ac[(r + 8) * 36 + kk + tig];
                a[mi][2] = Ac[r * 36 + kk + tig + 4];
                a[mi][3] = Ac[(r + 8) * 36 + kk + tig + 4];
            }
#pragma unroll
            for (int ni = 0; ni < 4; ni++) {
                int c = wn + ni * 8 + gid;
                bf[ni][0] = Bc[(kk + tig) * 132 + c];
                bf[ni][1] = Bc[(kk + tig + 4) * 132 + c];
            }
#pragma unroll
            for (int mi = 0; mi < 4; mi++)
#pragma unroll
                for (int ni = 0; ni < 4; ni++)
                    mma8(acc[mi][ni], a[mi], bf[ni]);
        }
        __syncthreads();
    }

    // epilogue
#pragma unroll
    for (int mi = 0; mi < 4; mi++) {
#pragma unroll
        for (int half = 0; half < 2; half++) {
            int rt = wm + mi * 16 + gid + half * 8;
            int cr = (map && !mapA) ? sMap[rt] : (m0 + rt);
            float scl = rowscale ? rowscale[(size_t)cr * rs_stride + rs_off] : 1.0f;
#pragma unroll
            for (int ni = 0; ni < 4; ni++) {
                int c = n0 + wn + ni * 8 + tig * 2;
                float v0 = acc[mi][ni][half * 2 + 0];
                float v1 = acc[mi][ni][half * 2 + 1];
                if (bias) { v0 += bias[c]; v1 += bias[c + 1]; }
                if (doGelu) { v0 = gelu_f(v0); v1 = gelu_f(v1); }
                v0 *= scl; v1 *= scl;
                float2* cp = (float2*)&Cp[(size_t)cr * ldc + c];
                if (doAccum) {
                    float2 o = *cp;
                    v0 += o.x; v1 += o.y;
                }
                *cp = make_float2(v0, v1);
            }
        }
    }
}

// ---------------------------------------------------------------------------
// Attention (mma.sync tensor cores)
// ---------------------------------------------------------------------------
__global__ __launch_bounds__(256) void attn_tc(
    const float* __restrict__ qkv, float* __restrict__ obuf) {
    extern __shared__ float sm[];
    float* Qs = sm;                    // [96][132]
    float* Ks = sm + 96 * 132;
    float* Vs = sm + 2 * 96 * 132;
    float* Ss = sm + 3 * 96 * 132;     // [96][100]

    int bh = blockIdx.x;
    int b = bh / 96, h = bh % 96;
    int tid = threadIdx.x;
    int lane = tid & 31, wid = tid >> 5;
    int gid = lane >> 2, tig = lane & 3;
    const float* base = qkv + (size_t)bh * 96 * 384;

    for (int f = tid; f < 96 * 96; f += 256) {
        int p = f / 96;
        int q = f % 96;
        int c = q * 4;
        float4 v = *(const float4*)&base[(size_t)p * 384 + c];
        if (c < 128) {
            v.x *= ATTN_SCALE; v.y *= ATTN_SCALE;
            v.z *= ATTN_SCALE; v.w *= ATTN_SCALE;
            *(float4*)&Qs[p * 132 + c] = v;
        } else if (c < 256) {
            *(float4*)&Ks[p * 132 + c - 128] = v;
        } else {
            *(float4*)&Vs[p * 132 + c - 256] = v;
        }
    }
    __syncthreads();

    {
        int wm = (wid >> 2) * 48, wn = (wid & 3) * 24;
        float acc[3][3][4] = {};
#pragma unroll
        for (int kk = 0; kk < 128; kk += 8) {
            float a[3][4], bf[3][2];
#pragma unroll
            for (int mi = 0; mi < 3; mi++) {
                int r = wm + mi * 16 + gid;
                a[mi][0] = Qs[r * 132 + kk + tig];
                a[mi][1] = Qs[(r + 8) * 132 + kk + tig];
                a[mi][2] = Qs[r * 132 + kk + tig + 4];
                a[mi][3] = Qs[(r + 8) * 132 + kk + tig + 4];
            }
#pragma unroll
            for (int ni = 0; ni < 3; ni++) {
                int c = wn + ni * 8 + gid;
                bf[ni][0] = Ks[c * 132 + kk + tig];
                bf[ni][1] = Ks[c * 132 + kk + tig + 4];
            }
#pragma unroll
            for (int mi = 0; mi < 3; mi++)
#pragma unroll
                for (int ni = 0; ni < 3; ni++)
                    mma8(acc[mi][ni], a[mi], bf[ni]);
        }
#pragma unroll
        for (int mi = 0; mi < 3; mi++)
#pragma unroll
            for (int half = 0; half < 2; half++) {
                int r = wm + mi * 16 + gid + half * 8;
#pragma unroll
                for (int ni = 0; ni < 3; ni++) {
                    int c = wn + ni * 8 + tig * 2;
                    Ss[r * 100 + c] = acc[mi][ni][half * 2 + 0];
                    Ss[r * 100 + c + 1] = acc[mi][ni][half * 2 + 1];
                }
            }
    }
    __syncthreads();

    {
        int w8 = tid >> 5, ln = tid & 31;
        for (int r = w8; r < 96; r += 8) {
            float v0 = Ss[r * 100 + ln];
            float v1 = Ss[r * 100 + 32 + ln];
            float v2 = Ss[r * 100 + 64 + ln];
            float m = fmaxf(v0, fmaxf(v1, v2));
#pragma unroll
            for (int o = 16; o > 0; o >>= 1)
                m = fmaxf(m, __shfl_xor_sync(0xffffffffu, m, o));
            float e0 = expf(v0 - m), e1 = expf(v1 - m), e2 = expf(v2 - m);
            float s = e0 + e1 + e2;
#pragma unroll
            for (int o = 16; o > 0; o >>= 1)
                s += __shfl_xor_sync(0xffffffffu, s, o);
            float inv = 1.0f / s;
            Ss[r * 100 + ln] = e0 * inv;
            Ss[r * 100 + 32 + ln] = e1 * inv;
            Ss[r * 100 + 64 + ln] = e2 * inv;
        }
    }
    __syncthreads();

    {
        int wm = (wid >> 2) * 48, wn = (wid & 3) * 32;
        float acc[3][4][4] = {};
#pragma unroll
        for (int kk = 0; kk < 96; kk += 8) {
            float a[3][4], bf[4][2];
#pragma unroll
            for (int mi = 0; mi < 3; mi++) {
                int r = wm + mi * 16 + gid;
                a[mi][0] = Ss[r * 100 + kk + tig];
                a[mi][1] = Ss[(r + 8) * 100 + kk + tig];
                a[mi][2] = Ss[r * 100 + kk + tig + 4];
                a[mi][3] = Ss[(r + 8) * 100 + kk + tig + 4];
            }
#pragma unroll
            for (int ni = 0; ni < 4; ni++) {
                int c = wn + ni * 8 + gid;
                bf[ni][0] = Vs[(kk + tig) * 132 + c];
                bf[ni][1] = Vs[(kk + tig + 4) * 132 + c];
            }
#pragma unroll
            for (int mi = 0; mi < 3; mi++)
#pragma unroll
                for (int ni = 0; ni < 4; ni++)
                    mma8(acc[mi][ni], a[mi], bf[ni]);
        }
#pragma unroll
        for (int mi = 0; mi < 3; mi++)
#pragma unroll
            for (int half = 0; half < 2; half++) {
                int q = wm + mi * 16 + gid + half * 8;
                int opix = (b * 96 + q) * 96 + h;
#pragma unroll
                for (int ni = 0; ni < 4; ni++) {
                    int c = wn + ni * 8 + tig * 2;
                    *(float2*)&obuf[(size_t)opix * HDIM + c] =
                        make_float2(acc[mi][ni][half * 2 + 0],
                                    acc[mi][ni][half * 2 + 1]);
                }
            }
    }
}

// ---------------------------------------------------------------------------
// MoE top-2 gating + expert index compaction
// ---------------------------------------------------------------------------
__global__ __launch_bounds__(256) void moe_gate_kernel(
    const float* __restrict__ xc, const float* __restrict__ wgf,
    float* __restrict__ mg, int* __restrict__ idx, int* __restrict__ cnt) {
    int gid = blockIdx.x * blockDim.x + threadIdx.x;
    int pix = gid >> 5;
    int lane = gid & 31;
    if (pix >= NPIX) return;
    const float* xp = xc + (size_t)pix * CH;
    float l0 = 0.f, l1 = 0.f, l2 = 0.f;
#pragma unroll
    for (int i = 0; i < 12; i++) {
        int c = i * 32 + lane;
        float xv = xp[c];
        l0 += xv * wgf[c * 3 + 0];
        l1 += xv * wgf[c * 3 + 1];
        l2 += xv * wgf[c * 3 + 2];
    }
#pragma unroll
    for (int o = 16; o > 0; o >>= 1) {
        l0 += __shfl_xor_sync(0xffffffffu, l0, o);
        l1 += __shfl_xor_sync(0xffffffffu, l1, o);
        l2 += __shfl_xor_sync(0xffffffffu, l2, o);
    }
    if (lane == 0) {
        float l[3] = {l0, l1, l2};
        int i0 = 0;
        if (l[1] > l[i0]) i0 = 1;
        if (l[2] > l[i0]) i0 = 2;
        int i1 = -1;
        for (int j = 0; j < 3; j++)
            if (j != i0 && (i1 < 0 || l[j] > l[i1])) i1 = j;
        float e1 = expf(l[i1] - l[i0]);
        float inv = 1.0f / (1.0f + e1);
        float g[3] = {0.f, 0.f, 0.f};
        g[i0] = inv;
        g[i1] = e1 * inv;
        mg[pix * 3 + 0] = g[0];
        mg[pix * 3 + 1] = g[1];
        mg[pix * 3 + 2] = g[2];
        int s0 = atomicAdd(&cnt[i0], 1);
        idx[i0 * NPAD + s0] = pix;
        int s1 = atomicAdd(&cnt[i1], 1);
        idx[i1 * NPAD + s1] = pix;
    }
}

// pad each expert's index list to a multiple of 128 with the dummy row NPIX
__global__ void pad_kernel(const int* __restrict__ cnt, int* __restrict__ idx,
                           int* __restrict__ cntp) {
    int e = blockIdx.x;
    int c = cnt[e];
    int p = (c + 127) & ~127;
    for (int i = c + threadIdx.x; i < p; i += blockDim.x)
        idx[e * NPAD + i] = NPIX;
    if (threadIdx.x == 0) cntp[e] = p;
}

// ---------------------------------------------------------------------------
// Host launcher
// ---------------------------------------------------------------------------
extern "C" void kernel_launch(void* const* d_in, const int* in_sizes, int n_in,
                              void* d_out, int out_size) {
    (void)in_sizes; (void)n_in; (void)out_size;
    const float* x = (const float*)d_in[0];
    const float* w_conv[6] = {(const float*)d_in[1], (const float*)d_in[3],
                              (const float*)d_in[5], (const float*)d_in[7],
                              (const float*)d_in[9], (const float*)d_in[11]};
    const float* b_conv[6] = {(const float*)d_in[2], (const float*)d_in[4],
                              (const float*)d_in[6], (const float*)d_in[8],
                              (const float*)d_in[10], (const float*)d_in[12]};
    const float* wg1 = (const float*)d_in[13];
    const float* wg2 = (const float*)d_in[14];
    const float* wg3 = (const float*)d_in[15];
    const float* w_qkv = (const float*)d_in[16];
    const float* w_ap  = (const float*)d_in[17];
    const float* b_ap  = (const float*)d_in[18];
    const float* wgf   = (const float*)d_in[19];
    const float* w1    = (const float*)d_in[20];
    const float* b1    = (const float*)d_in[21];
    const float* w2    = (const float*)d_in[22];
    const float* b2    = (const float*)d_in[23];
    const float* wp    = (const float*)d_in[24];
    const float* bp    = (const float*)d_in[25];
    float* out = (float*)d_out;

    float *gates, *moe, *qkv, *obuf, *xc, *mgate, *hidden, *accum;
    int *midx, *cnt, *cntp;
    cudaGetSymbolAddress((void**)&gates, g_gates);
    cudaGetSymbolAddress((void**)&moe, g_moe);
    cudaGetSymbolAddress((void**)&qkv, g_qkv);
    cudaGetSymbolAddress((void**)&obuf, g_obuf);
    cudaGetSymbolAddress((void**)&xc, g_xc);
    cudaGetSymbolAddress((void**)&mgate, g_mgate);
    cudaGetSymbolAddress((void**)&hidden, g_hidden);
    cudaGetSymbolAddress((void**)&accum, g_accum);
    cudaGetSymbolAddress((void**)&midx, g_midx);
    cudaGetSymbolAddress((void**)&cnt, g_cnt);
    cudaGetSymbolAddress((void**)&cntp, g_cntp);

    cudaFuncSetAttribute(attn_tc, cudaFuncAttributeMaxDynamicSharedMemorySize,
                         ATTN_SMEM_BYTES);
    cudaFuncSetAttribute(conv_moe_tc, cudaFuncAttributeMaxDynamicSharedMemorySize,
                         CONV_SMEM_BYTES);
    cudaFuncSetAttribute(gemm_tc, cudaFuncAttributeMaxDynamicSharedMemorySize,
                         GEMM_SMEM_BYTES);

    // reset routing state + output accumulator (async, capturable)
    cudaMemsetAsync(cnt, 0, 3 * sizeof(int));
    cudaMemsetAsync(accum, 0, (size_t)NPIX * CH * sizeof(float));

    // 1. per-branch 2-way gates
    branch_gate_kernel<<<NPIX / 8, 256>>>(x, wg1, wg2, wg3, gates);

    // 2. branches
    for (int br = 0; br < 3; br++) {
        conv_moe_tc<<<dim3(3 * HGT, BATCH), 256, CONV_SMEM_BYTES>>>(
            x, w_conv[2 * br], b_conv[2 * br], w_conv[2 * br + 1],
            b_conv[2 * br + 1], gates, br, moe);
        gemm_tc<<<dim3((3 * HDIM) / 128, NPIX / 128), 256, GEMM_SMEM_BYTES>>>(
            moe, HDIM, w_qkv + (size_t)br * HDIM * 3 * HDIM, 3 * HDIM,
            nullptr, nullptr, 0, 0, qkv, 3 * HDIM, HDIM, 0, 0,
            nullptr, 0, nullptr);
        attn_tc<<<BATCH * HGT, 256, ATTN_SMEM_BYTES>>>(qkv, obuf);
        gemm_tc<<<dim3(HDIM / 128, NPIX / 128), 256, GEMM_SMEM_BYTES>>>(
            obuf, HDIM, w_ap + (size_t)br * HDIM * HDIM, HDIM,
            b_ap + (size_t)br * HDIM, nullptr, 0, 0,
            xc + br * HDIM, CH, HDIM, 0, 0, nullptr, 0, nullptr);
    }

    // 3. top-2 MoE gates + compaction + padding
    moe_gate_kernel<<<NPIX / 8, 256>>>(xc, wgf, mgate, midx, cnt);
    pad_kernel<<<3, 128>>>(cnt, midx, cntp);

    // 4. sparse 2-of-3 expert MLP (gather rows -> hidden; scatter-accum out)
    for (int e = 0; e < 3; e++) {
        gemm_tc<<<dim3(MLPH / 128, NPIX / 128), 256, GEMM_SMEM_BYTES>>>(
            xc, CH, w1 + (size_t)e * CH * MLPH, MLPH, b1 + (size_t)e * MLPH,
            nullptr, 0, 0, hidden, MLPH, CH, 1, 0,
            midx + e * NPAD, 1, cntp + e);
        gemm_tc<<<dim3(CH / 128, NPIX / 128), 256, GEMM_SMEM_BYTES>>>(
            hidden, MLPH, w2 + (size_t)e * MLPH * CH, CH, b2 + (size_t)e * CH,
            mgate, 3, e, accum, CH, MLPH, 0, 1,
            midx + e * NPAD, 0, cntp + e);
    }

    // 5. final projection
    gemm_tc<<<dim3(CH / 128, NPIX / 128), 256, GEMM_SMEM_BYTES>>>(
        accum, CH, wp, CH, bp, nullptr, 0, 0, out, CH, CH, 0, 0,
        nullptr, 0, nullptr);
}

// round 7
// speedup vs baseline: 5.9144x; 1.6092x over previous
#include <cuda_runtime.h>
#include <cuda_fp16.h>
#include <math.h>
#include <cstddef>

// ---------------------------------------------------------------------------
// Problem constants
// ---------------------------------------------------------------------------
namespace {
constexpr int BATCH = 4, HGT = 96, WID = 96, CH = 384, HDIM = 128;
constexpr int NPIX = BATCH * HGT * WID;   // 36864
constexpr int NPAD = NPIX + 128;
constexpr int MLPH = 4 * CH;              // 1536
constexpr float ATTN_SCALE = 0.15430334996209191f; // (128//3)^-0.5
constexpr int ATTN_SMEM_BYTES = (3 * 96 * 132 + 96 * 100) * 4;        // 190464
// conv: A [2][32][136]h + W [2][64][136]h
constexpr int CONVH_SMEM_BYTES = (2 * 32 * 136 + 2 * 64 * 136) * 2;   // 52224
// gemm: A [2][128][40]h + B [2][32][136]h
constexpr int GH_SMEM_BYTES = (2 * 128 * 40 + 2 * 32 * 136) * 2;      // 37888
}

// ---------------------------------------------------------------------------
// Scratch (device globals)
// ---------------------------------------------------------------------------
__device__ float g_gates[NPIX * 6];
__device__ float g_qkv[(size_t)NPIX * 3 * HDIM];
__device__ float g_xc[(size_t)NPAD * CH];
__device__ float g_mgate[NPAD * 3];
__device__ float g_accum[(size_t)NPAD * CH];
__device__ int g_midx[3 * NPAD];
__device__ int g_cnt[3];
__device__ int g_cntp[3];
// fp16 tensors
__device__ __half g_xh[(size_t)NPIX * CH];
__device__ __half g_wch[6 * 9 * 128 * 128];
__device__ __half g_wqkvh[3 * 128 * 384];
__device__ __half g_waph[3 * 128 * 128];
__device__ __half g_w1h[(size_t)3 * 384 * 1536];
__device__ __half g_w2h[(size_t)3 * 1536 * 384];
__device__ __half g_wph[384 * 384];
__device__ __half g_moeh[(size_t)NPIX * HDIM];
__device__ __half g_obufh[(size_t)NPIX * HDIM];
__device__ __half g_xch[(size_t)NPAD * CH];
__device__ __half g_hiddenh[(size_t)NPAD * MLPH];
__device__ __half g_accumh[(size_t)NPAD * CH];

__device__ __forceinline__ float gelu_f(float v) {
    float u = 0.7978845608028654f * (v + 0.044715f * v * v * v);
    return 0.5f * v * (1.0f + tanhf(u));
}

// ---------------------------------------------------------------------------
// PTX helpers
// ---------------------------------------------------------------------------
__device__ __forceinline__ unsigned smem_u32p(const void* p) {
    return (unsigned)__cvta_generic_to_shared(p);
}
__device__ __forceinline__ void cp16(const void* dst, const void* src) {
    asm volatile("cp.async.cg.shared.global [%0],[%1],16;"
                 :: "r"(smem_u32p(dst)), "l"(src));
}
__device__ __forceinline__ void cp16z(const void* dst, const void* src, int sz) {
    asm volatile("cp.async.cg.shared.global [%0],[%1],16,%2;"
                 :: "r"(smem_u32p(dst)), "l"(src), "r"(sz));
}
__device__ __forceinline__ void cp_commit() {
    asm volatile("cp.async.commit_group;");
}
template <int N>
__device__ __forceinline__ void cp_wait() {
    asm volatile("cp.async.wait_group %0;" :: "n"(N));
}
// fp16 m16n8k16 mma, fp32 accum
__device__ __forceinline__ void mma16(float* c, const unsigned* a, const unsigned* b) {
    asm volatile(
        "mma.sync.aligned.m16n8k16.row.col.f32.f16.f16.f32 "
        "{%0,%1,%2,%3}, {%4,%5,%6,%7}, {%8,%9}, {%0,%1,%2,%3};"
        : "+f"(c[0]), "+f"(c[1]), "+f"(c[2]), "+f"(c[3])
        : "r"(a[0]), "r"(a[1]), "r"(a[2]), "r"(a[3]), "r"(b[0]), "r"(b[1]));
}
// tf32 m16n8k8 (attention only)
__device__ __forceinline__ void mma8(float* c, const float* a, const float* b) {
    asm volatile(
        "mma.sync.aligned.m16n8k8.row.col.f32.tf32.tf32.f32 "
        "{%0,%1,%2,%3}, {%4,%5,%6,%7}, {%8,%9}, {%0,%1,%2,%3};"
        : "+f"(c[0]), "+f"(c[1]), "+f"(c[2]), "+f"(c[3])
        : "r"(__float_as_uint(a[0])), "r"(__float_as_uint(a[1])),
          "r"(__float_as_uint(a[2])), "r"(__float_as_uint(a[3])),
          "r"(__float_as_uint(b[0])), "r"(__float_as_uint(b[1])));
}
__device__ __forceinline__ void ldsm_x4(unsigned* r, unsigned addr) {
    asm volatile("ldmatrix.sync.aligned.m8n8.x4.shared.b16 {%0,%1,%2,%3},[%4];"
                 : "=r"(r[0]), "=r"(r[1]), "=r"(r[2]), "=r"(r[3]) : "r"(addr));
}
__device__ __forceinline__ void ldsm_x4t(unsigned* r, unsigned addr) {
    asm volatile("ldmatrix.sync.aligned.m8n8.x4.trans.shared.b16 {%0,%1,%2,%3},[%4];"
                 : "=r"(r[0]), "=r"(r[1]), "=r"(r[2]), "=r"(r[3]) : "r"(addr));
}

// ---------------------------------------------------------------------------
// fp32 -> fp16 conversion (RN)
// ---------------------------------------------------------------------------
__global__ __launch_bounds__(256) void f2h_kernel(
    const float* __restrict__ s, __half* __restrict__ d, int n4) {
    int i = blockIdx.x * blockDim.x + threadIdx.x;
    if (i >= n4) return;
    float4 v = ((const float4*)s)[i];
    __half2* dp = (__half2*)d + i * 2;
    dp[0] = __floats2half2_rn(v.x, v.y);
    dp[1] = __floats2half2_rn(v.z, v.w);
}

// ---------------------------------------------------------------------------
// Branch gating (warp per pixel)
// ---------------------------------------------------------------------------
__device__ __forceinline__ void bg_dot(const float* xp, const float* wg, int lane,
                                       float& g0, float& g1) {
    float a0 = 0.f, a1 = 0.f;
#pragma unroll
    for (int i = 0; i < 4; i++) {
        int c = i * 32 + lane;
        float xv = xp[c];
        a0 += xv * wg[c * 2 + 0];
        a1 += xv * wg[c * 2 + 1];
    }
#pragma unroll
    for (int o = 16; o > 0; o >>= 1) {
        a0 += __shfl_xor_sync(0xffffffffu, a0, o);
        a1 += __shfl_xor_sync(0xffffffffu, a1, o);
    }
    float m = fmaxf(a0, a1);
    float e0 = expf(a0 - m), e1 = expf(a1 - m);
    float inv = 1.0f / (e0 + e1);
    g0 = e0 * inv;
    g1 = e1 * inv;
}

__global__ __launch_bounds__(256) void branch_gate_kernel(
    const float* __restrict__ x, const float* __restrict__ wg1,
    const float* __restrict__ wg2, const float* __restrict__ wg3,
    float* __restrict__ gates) {
    int gid = blockIdx.x * blockDim.x + threadIdx.x;
    int pix = gid >> 5;
    int lane = gid & 31;
    if (pix >= NPIX) return;
    const float* xp = x + (size_t)pix * CH;
    float g0, g1;
    bg_dot(xp + 0 * HDIM, wg1, lane, g0, g1);
    if (lane == 0) { gates[pix * 6 + 0] = g0; gates[pix * 6 + 1] = g1; }
    bg_dot(xp + 1 * HDIM, wg2, lane, g0, g1);
    if (lane == 0) { gates[pix * 6 + 2] = g0; gates[pix * 6 + 3] = g1; }
    bg_dot(xp + 2 * HDIM, wg3, lane, g0, g1);
    if (lane == 0) { gates[pix * 6 + 4] = g0; gates[pix * 6 + 5] = g1; }
}

// ---------------------------------------------------------------------------
// Fused dual-conv + gate, fp16 mma (m16n8k16), cp.async pipelined.
// A [32 pix][128 ch] fp16 (x pre-converted), W per-tap fp16.
// 36 steps = 18 taps x 2 K-chunks of 64. Warp tile 32x16.
// ---------------------------------------------------------------------------
__global__ __launch_bounds__(256) void conv_moe_h(
    const __half* __restrict__ xh,
    const __half* __restrict__ wa, const float* __restrict__ ba,
    const __half* __restrict__ wb, const float* __restrict__ bb,
    const float* __restrict__ gates, int br, __half* __restrict__ moeh) {
    extern __shared__ __half chs[];
    __half* sA = chs;                    // [2][32*136]
    __half* sW = chs + 2 * 32 * 136;     // [2][64*136]
    __shared__ float sGA[32], sGB[32];

    int tid = threadIdx.x;
    int lane = tid & 31, wid = tid >> 5;
    int gid = lane >> 2, tig = lane & 3;
    int wn = wid * 16;

    int wc = blockIdx.x % 3;
    int h = blockIdx.x / 3;
    int b = blockIdx.y;
    int w0 = wc * 32;
    int pixbase = (b * HGT + h) * WID + w0;

    if (tid < 32) {
        sGA[tid] = gates[(size_t)(pixbase + tid) * 6 + br * 2 + 0];
        sGB[tid] = gates[(size_t)(pixbase + tid) * 6 + br * 2 + 1];
    }

    auto geo = [&](int t, int& dh, int& dw) {
        int tc = t % 9;
        int isB = (t >= 9);
        if (br == 0)      { dh = tc / 3 - 1; dw = tc % 3 - 1; }
        else if (br == 1) { dh = tc - 4;     dw = 0;          }
        else              { dh = 0;          dw = tc - 4;     }
        if (isB) { dh *= 2; dw *= 2; }
    };

    auto loadA = [&](int t, int buf) {
        int dh, dw;
        geo(t, dh, dw);
        int hh = h + dh;
        __half* dstb = sA + buf * (32 * 136);
#pragma unroll
        for (int l = 0; l < 2; l++) {
            int f = tid + l * 256;          // 0..511
            int p = f >> 4;                 // pixel 0..31
            int c8 = (f & 15) * 8;          // 0..120
            int wv = w0 + p + dw;
            bool ok = (hh >= 0 && hh < HGT && wv >= 0 && wv < WID);
            const __half* src = ok
                ? &xh[((size_t)((b * HGT + hh) * WID + wv)) * CH + br * HDIM + c8]
                : xh;
            cp16z(dstb + p * 136 + c8, src, ok ? 16 : 0);
        }
    };

    auto loadW = [&](int s, int buf) {
        int t = s >> 1, chunk = s & 1;
        int tc = t % 9;
        const __half* wt = ((t >= 9) ? wb : wa) + (size_t)tc * (HDIM * HDIM);
        __half* dstb = sW + buf * (64 * 136);
#pragma unroll
        for (int l = 0; l < 4; l++) {
            int f = tid + l * 256;          // 0..1023
            int k = f >> 4;                 // 0..63
            int c8 = (f & 15) * 8;
            cp16(dstb + k * 136 + c8, &wt[(size_t)(chunk * 64 + k) * HDIM + c8]);
        }
    };

    loadA(0, 0);
    loadW(0, 0);
    cp_commit();

    float accA[2][2][4] = {};
    float accB[2][2][4] = {};

    for (int s = 0; s < 36; s++) {
        int tap = s >> 1;
        if (s + 1 < 36) loadW(s + 1, (s + 1) & 1);
        if ((s & 1) == 0 && tap + 1 < 18) loadA(tap + 1, (tap + 1) & 1);
        cp_commit();
        cp_wait<1>();
        __syncthreads();

        const __half* Ac = sA + (tap & 1) * (32 * 136);
        const __half* Wc = sW + (s & 1) * (64 * 136);
        int kgb = (s & 1) * 64;
        float (*acc)[2][4] = (tap < 9) ? accA : accB;

#pragma unroll
        for (int kk = 0; kk < 64; kk += 16) {
            unsigned a[2][4], bq[4];
#pragma unroll
            for (int mi = 0; mi < 2; mi++) {
                int r = mi * 16 + (lane & 15);
                int c = kgb + kk + (lane >> 4) * 8;
                ldsm_x4(a[mi], smem_u32p(Ac + r * 136 + c));
            }
            {
                int kr = kk + (lane & 15);
                int c = wn + (lane >> 4) * 8;
                ldsm_x4t(bq, smem_u32p(Wc + kr * 136 + c));
            }
#pragma unroll
            for (int mi = 0; mi < 2; mi++)
#pragma unroll
                for (int ni = 0; ni < 2; ni++)
                    mma16(acc[mi][ni], a[mi], &bq[ni * 2]);
        }
        __syncthreads();
    }

    // epilogue: moe = gA*(accA+ba) + gB*(accB+bb), stored fp16
#pragma unroll
    for (int mi = 0; mi < 2; mi++) {
#pragma unroll
        for (int half = 0; half < 2; half++) {
            int p = mi * 16 + gid + half * 8;
            float gg0 = sGA[p], gg1 = sGB[p];
#pragma unroll
            for (int ni = 0; ni < 2; ni++) {
                int c = wn + ni * 8 + tig * 2;
                float v0 = gg0 * (accA[mi][ni][half * 2 + 0] + ba[c]) +
                           gg1 * (accB[mi][ni][half * 2 + 0] + bb[c]);
                float v1 = gg0 * (accA[mi][ni][half * 2 + 1] + ba[c + 1]) +
                           gg1 * (accB[mi][ni][half * 2 + 1] + bb[c + 1]);
                *(__half2*)&moeh[(size_t)(pixbase + p) * HDIM + c] =
                    __floats2half2_rn(v0, v1);
            }
        }
    }
}

// ---------------------------------------------------------------------------
// fp16 tensor-core GEMM, cp.async 2-stage, ldmatrix fragments.
// BM=BN=128, BK=32, warp tile 64x32. Optional gather/scatter via map,
// dual fp32/fp16 outputs, bias/gelu/rowscale/accumulate.
// ---------------------------------------------------------------------------
__global__ __launch_bounds__(256, 2) void gemm_h(
    const __half* __restrict__ A, int lda,
    const __half* __restrict__ B, int ldb,
    const float* __restrict__ bias,
    const float* __restrict__ rowscale, int rs_stride, int rs_off,
    float* __restrict__ Cf, __half* __restrict__ Ch, int ldc,
    int K, int doGelu, int doAccum,
    const int* __restrict__ map, int mapA, const int* __restrict__ cntp) {
    extern __shared__ __half hsm[];
    __half* sA = hsm;                    // [2][128*40]
    __half* sB = hsm + 2 * 128 * 40;     // [2][32*136]
    __shared__ int sMap[128];

    int tid = threadIdx.x;
    int m0 = blockIdx.y * 128, n0 = blockIdx.x * 128;
    if (cntp && m0 >= *cntp) return;

    int lane = tid & 31, wid = tid >> 5;
    int gid = lane >> 2, tig = lane & 3;
    int wm = (wid >> 2) * 64, wn = (wid & 3) * 32;

    if (map) {
        if (tid < 128) sMap[tid] = map[m0 + tid];
        __syncthreads();
    }

    auto loadA = [&](int k0, __half* dst) {
#pragma unroll
        for (int l = 0; l < 2; l++) {
            int f = tid + l * 256;          // 0..511
            int r = f >> 2;                 // 0..127
            int c8 = (f & 3) * 8;           // 0..24
            int ar = (map && mapA) ? sMap[r] : (m0 + r);
            cp16(dst + r * 40 + c8, &A[(size_t)ar * lda + k0 + c8]);
        }
    };
    auto loadB = [&](int k0, __half* dst) {
#pragma unroll
        for (int l = 0; l < 2; l++) {
            int f = tid + l * 256;
            int r = f >> 4;                 // 0..31
            int c8 = (f & 15) * 8;
            cp16(dst + r * 136 + c8, &B[(size_t)(k0 + r) * ldb + n0 + c8]);
        }
    };

    int nk = K / 32;
    loadA(0, sA);
    loadB(0, sB);
    cp_commit();

    float acc[4][4][4] = {};

    for (int i = 0; i < nk; i++) {
        if (i + 1 < nk) {
            loadA((i + 1) * 32, sA + ((i + 1) & 1) * (128 * 40));
            loadB((i + 1) * 32, sB + ((i + 1) & 1) * (32 * 136));
        }
        cp_commit();
        cp_wait<1>();
        __syncthreads();

        const __half* Ac = sA + (i & 1) * (128 * 40);
        const __half* Bc = sB + (i & 1) * (32 * 136);
#pragma unroll
        for (int kk = 0; kk < 32; kk += 16) {
            unsigned a[4][4], bq[2][4];
#pragma unroll
            for (int mi = 0; mi < 4; mi++) {
                int r = wm + mi * 16 + (lane & 15);
                int c = kk + (lane >> 4) * 8;
                ldsm_x4(a[mi], smem_u32p(Ac + r * 40 + c));
            }
#pragma unroll
            for (int p = 0; p < 2; p++) {
                int kr = kk + (lane & 15);
                int c = wn + p * 16 + (lane >> 4) * 8;
                ldsm_x4t(bq[p], smem_u32p(Bc + kr * 136 + c));
            }
#pragma unroll
            for (int mi = 0; mi < 4; mi++)
#pragma unroll
                for (int ni = 0; ni < 4; ni++)
                    mma16(acc[mi][ni], a[mi], &bq[ni >> 1][(ni & 1) * 2]);
        }
        __syncthreads();
    }

    // epilogue
#pragma unroll
    for (int mi = 0; mi < 4; mi++) {
#pragma unroll
        for (int half = 0; half < 2; half++) {
            int rt = wm + mi * 16 + gid + half * 8;
            int cr = (map && !mapA) ? sMap[rt] : (m0 + rt);
            float scl = rowscale ? rowscale[(size_t)cr * rs_stride + rs_off] : 1.0f;
#pragma unroll
            for (int ni = 0; ni < 4; ni++) {
                int c = n0 + wn + ni * 8 + tig * 2;
                float v0 = acc[mi][ni][half * 2 + 0];
                float v1 = acc[mi][ni][half * 2 + 1];
                if (bias) { v0 += bias[c]; v1 += bias[c + 1]; }
                if (doGelu) { v0 = gelu_f(v0); v1 = gelu_f(v1); }
                v0 *= scl; v1 *= scl;
                if (Cf) {
                    float2* cp = (float2*)&Cf[(size_t)cr * ldc + c];
                    if (doAccum) {
                        float2 o = *cp;
                        v0 += o.x; v1 += o.y;
                    }
                    *cp = make_float2(v0, v1);
                }
                if (Ch) {
                    *(__half2*)&Ch[(size_t)cr * ldc + c] = __floats2half2_rn(v0, v1);
                }
            }
        }
    }
}

// ---------------------------------------------------------------------------
// Attention (tf32 mma.sync) — reads fp32 qkv, writes fp16 obuf
// ---------------------------------------------------------------------------
__global__ __launch_bounds__(256) void attn_tc(
    const float* __restrict__ qkv, __half* __restrict__ obufh) {
    extern __shared__ float sm[];
    float* Qs = sm;                    // [96][132]
    float* Ks = sm + 96 * 132;
    float* Vs = sm + 2 * 96 * 132;
    float* Ss = sm + 3 * 96 * 132;     // [96][100]

    int bh = blockIdx.x;
    int b = bh / 96, h = bh % 96;
    int tid = threadIdx.x;
    int lane = tid & 31, wid = tid >> 5;
    int gid = lane >> 2, tig = lane & 3;
    const float* base = qkv + (size_t)bh * 96 * 384;

    for (int f = tid; f < 96 * 96; f += 256) {
        int p = f / 96;
        int q = f % 96;
        int c = q * 4;
        float4 v = *(const float4*)&base[(size_t)p * 384 + c];
        if (c < 128) {
            v.x *= ATTN_SCALE; v.y *= ATTN_SCALE;
            v.z *= ATTN_SCALE; v.w *= ATTN_SCALE;
            *(float4*)&Qs[p * 132 + c] = v;
        } else if (c < 256) {
            *(float4*)&Ks[p * 132 + c - 128] = v;
        } else {
            *(float4*)&Vs[p * 132 + c - 256] = v;
        }
    }
    __syncthreads();

    {
        int wm = (wid >> 2) * 48, wn = (wid & 3) * 24;
        float acc[3][3][4] = {};
#pragma unroll
        for (int kk = 0; kk < 128; kk += 8) {
            float a[3][4], bf[3][2];
#pragma unroll
            for (int mi = 0; mi < 3; mi++) {
                int r = wm + mi * 16 + gid;
                a[mi][0] = Qs[r * 132 + kk + tig];
                a[mi][1] = Qs[(r + 8) * 132 + kk + tig];
                a[mi][2] = Qs[r * 132 + kk + tig + 4];
                a[mi][3] = Qs[(r + 8) * 132 + kk + tig + 4];
            }
#pragma unroll
            for (int ni = 0; ni < 3; ni++) {
                int c = wn + ni * 8 + gid;
                bf[ni][0] = Ks[c * 132 + kk + tig];
                bf[ni][1] = Ks[c * 132 + kk + tig + 4];
            }
#pragma unroll
            for (int mi = 0; mi < 3; mi++)
#pragma unroll
                for (int ni = 0; ni < 3; ni++)
                    mma8(acc[mi][ni], a[mi], bf[ni]);
        }
#pragma unroll
        for (int mi = 0; mi < 3; mi++)
#pragma unroll
            for (int half = 0; half < 2; half++) {
                int r = wm + mi * 16 + gid + half * 8;
#pragma unroll
                for (int ni = 0; ni < 3; ni++) {
                    int c = wn + ni * 8 + tig * 2;
                    Ss[r * 100 + c] = acc[mi][ni][half * 2 + 0];
                    Ss[r * 100 + c + 1] = acc[mi][ni][half * 2 + 1];
                }
            }
    }
    __syncthreads();

    {
        int w8 = tid >> 5, ln = tid & 31;
        for (int r = w8; r < 96; r += 8) {
            float v0 = Ss[r * 100 + ln];
            float v1 = Ss[r * 100 + 32 + ln];
            float v2 = Ss[r * 100 + 64 + ln];
            float m = fmaxf(v0, fmaxf(v1, v2));
#pragma unroll
            for (int o = 16; o > 0; o >>= 1)
                m = fmaxf(m, __shfl_xor_sync(0xffffffffu, m, o));
            float e0 = expf(v0 - m), e1 = expf(v1 - m), e2 = expf(v2 - m);
            float s = e0 + e1 + e2;
#pragma unroll
            for (int o = 16; o > 0; o >>= 1)
                s += __shfl_xor_sync(0xffffffffu, s, o);
            float inv = 1.0f / s;
            Ss[r * 100 + ln] = e0 * inv;
            Ss[r * 100 + 32 + ln] = e1 * inv;
            Ss[r * 100 + 64 + ln] = e2 * inv;
        }
    }
    __syncthreads();

    {
        int wm = (wid >> 2) * 48, wn = (wid & 3) * 32;
        float acc[3][4][4] = {};
#pragma unroll
        for (int kk = 0; kk < 96; kk += 8) {
            float a[3][4], bf[4][2];
#pragma unroll
            for (int mi = 0; mi < 3; mi++) {
                int r = wm + mi * 16 + gid;
                a[mi][0] = Ss[r * 100 + kk + tig];
                a[mi][1] = Ss[(r + 8) * 100 + kk + tig];
                a[mi][2] = Ss[r * 100 + kk + tig + 4];
                a[mi][3] = Ss[(r + 8) * 100 + kk + tig + 4];
            }
#pragma unroll
            for (int ni = 0; ni < 4; ni++) {
                int c = wn + ni * 8 + gid;
                bf[ni][0] = Vs[(kk + tig) * 132 + c];
                bf[ni][1] = Vs[(kk + tig + 4) * 132 + c];
            }
#pragma unroll
            for (int mi = 0; mi < 3; mi++)
#pragma unroll
                for (int ni = 0; ni < 4; ni++)
                    mma8(acc[mi][ni], a[mi], bf[ni]);
        }
#pragma unroll
        for (int mi = 0; mi < 3; mi++)
#pragma unroll
            for (int half = 0; half < 2; half++) {
                int q = wm + mi * 16 + gid + half * 8;
                int opix = (b * 96 + q) * 96 + h;
#pragma unroll
                for (int ni = 0; ni < 4; ni++) {
                    int c = wn + ni * 8 + tig * 2;
                    *(__half2*)&obufh[(size_t)opix * HDIM + c] =
                        __floats2half2_rn(acc[mi][ni][half * 2 + 0],
                                          acc[mi][ni][half * 2 + 1]);
                }
            }
    }
}

// ---------------------------------------------------------------------------
// MoE top-2 gating + expert index compaction
// ---------------------------------------------------------------------------
__global__ __launch_bounds__(256) void moe_gate_kernel(
    const float* __restrict__ xc, const float* __restrict__ wgf,
    float* __restrict__ mg, int* __restrict__ idx, int* __restrict__ cnt) {
    int gid = blockIdx.x * blockDim.x + threadIdx.x;
    int pix = gid >> 5;
    int lane = gid & 31;
    if (pix >= NPIX) return;
    const float* xp = xc + (size_t)pix * CH;
    float l0 = 0.f, l1 = 0.f, l2 = 0.f;
#pragma unroll
    for (int i = 0; i < 12; i++) {
        int c = i * 32 + lane;
        float xv = xp[c];
        l0 += xv * wgf[c * 3 + 0];
        l1 += xv * wgf[c * 3 + 1];
        l2 += xv * wgf[c * 3 + 2];
    }
#pragma unroll
    for (int o = 16; o > 0; o >>= 1) {
        l0 += __shfl_xor_sync(0xffffffffu, l0, o);
        l1 += __shfl_xor_sync(0xffffffffu, l1, o);
        l2 += __shfl_xor_sync(0xffffffffu, l2, o);
    }
    if (lane == 0) {
        float l[3] = {l0, l1, l2};
        int i0 = 0;
        if (l[1] > l[i0]) i0 = 1;
        if (l[2] > l[i0]) i0 = 2;
        int i1 = -1;
        for (int j = 0; j < 3; j++)
            if (j != i0 && (i1 < 0 || l[j] > l[i1])) i1 = j;
        float e1 = expf(l[i1] - l[i0]);
        float inv = 1.0f / (1.0f + e1);
        float g[3] = {0.f, 0.f, 0.f};
        g[i0] = inv;
        g[i1] = e1 * inv;
        mg[pix * 3 + 0] = g[0];
        mg[pix * 3 + 1] = g[1];
        mg[pix * 3 + 2] = g[2];
        int s0 = atomicAdd(&cnt[i0], 1);
        idx[i0 * NPAD + s0] = pix;
        int s1 = atomicAdd(&cnt[i1], 1);
        idx[i1 * NPAD + s1] = pix;
    }
}

// pad each expert's index list to a multiple of 128 with the dummy row NPIX
__global__ void pad_kernel(const int* __restrict__ cnt, int* __restrict__ idx,
                           int* __restrict__ cntp) {
    int e = blockIdx.x;
    int c = cnt[e];
    int p = (c + 127) & ~127;
    for (int i = c + threadIdx.x; i < p; i += blockDim.x)
        idx[e * NPAD + i] = NPIX;
    if (threadIdx.x == 0) cntp[e] = p;
}

// ---------------------------------------------------------------------------
// Host launcher
// ---------------------------------------------------------------------------
extern "C" void kernel_launch(void* const* d_in, const int* in_sizes, int n_in,
                              void* d_out, int out_size) {
    (void)in_sizes; (void)n_in; (void)out_size;
    const float* x = (const float*)d_in[0];
    const float* w_conv[6] = {(const float*)d_in[1], (const float*)d_in[3],
                              (const float*)d_in[5], (const float*)d_in[7],
                              (const float*)d_in[9], (const float*)d_in[11]};
    const float* b_conv[6] = {(const float*)d_in[2], (const float*)d_in[4],
                              (const float*)d_in[6], (const float*)d_in[8],
                              (const float*)d_in[10], (const float*)d_in[12]};
    const float* wg1 = (const float*)d_in[13];
    const float* wg2 = (const float*)d_in[14];
    const float* wg3 = (const float*)d_in[15];
    const float* w_qkv = (const float*)d_in[16];
    const float* w_ap  = (const float*)d_in[17];
    const float* b_ap  = (const float*)d_in[18];
    const float* wgf   = (const float*)d_in[19];
    const float* w1    = (const float*)d_in[20];
    const float* b1    = (const float*)d_in[21];
    const float* w2    = (const float*)d_in[22];
    const float* b2    = (const float*)d_in[23];
    const float* wp    = (const float*)d_in[24];
    const float* bp    = (const float*)d_in[25];
    float* out = (float*)d_out;

    float *gates, *qkv, *xc, *mgate, *accum;
    int *midx, *cnt, *cntp;
    __half *xh, *wch, *wqkvh, *waph, *w1h, *w2h, *wph;
    __half *moeh, *obufh, *xch, *hiddenh, *accumh;
    cudaGetSymbolAddress((void**)&gates, g_gates);
    cudaGetSymbolAddress((void**)&qkv, g_qkv);
    cudaGetSymbolAddress((void**)&xc, g_xc);
    cudaGetSymbolAddress((void**)&mgate, g_mgate);
    cudaGetSymbolAddress((void**)&accum, g_accum);
    cudaGetSymbolAddress((void**)&midx, g_midx);
    cudaGetSymbolAddress((void**)&cnt, g_cnt);
    cudaGetSymbolAddress((void**)&cntp, g_cntp);
    cudaGetSymbolAddress((void**)&xh, g_xh);
    cudaGetSymbolAddress((void**)&wch, g_wch);
    cudaGetSymbolAddress((void**)&wqkvh, g_wqkvh);
    cudaGetSymbolAddress((void**)&waph, g_waph);
    cudaGetSymbolAddress((void**)&w1h, g_w1h);
    cudaGetSymbolAddress((void**)&w2h, g_w2h);
    cudaGetSymbolAddress((void**)&wph, g_wph);
    cudaGetSymbolAddress((void**)&moeh, g_moeh);
    cudaGetSymbolAddress((void**)&obufh, g_obufh);
    cudaGetSymbolAddress((void**)&xch, g_xch);
    cudaGetSymbolAddress((void**)&hiddenh, g_hiddenh);
    cudaGetSymbolAddress((void**)&accumh, g_accumh);

    cudaFuncSetAttribute(attn_tc, cudaFuncAttributeMaxDynamicSharedMemorySize,
                         ATTN_SMEM_BYTES);
    cudaFuncSetAttribute(conv_moe_h, cudaFuncAttributeMaxDynamicSharedMemorySize,
                         CONVH_SMEM_BYTES);
    cudaFuncSetAttribute(gemm_h, cudaFuncAttributeMaxDynamicSharedMemorySize,
                         GH_SMEM_BYTES);

    auto f2h = [](const float* s, __half* d, size_t n) {
        int n4 = (int)(n / 4);
        f2h_kernel<<<(n4 + 255) / 256, 256>>>(s, d, n4);
    };

    // reset routing state + output accumulator
    cudaMemsetAsync(cnt, 0, 3 * sizeof(int));
    cudaMemsetAsync(accum, 0, (size_t)NPIX * CH * sizeof(float));

    // 0. fp16 conversions (weights + input)
    f2h(x, xh, (size_t)NPIX * CH);
    for (int i = 0; i < 6; i++)
        f2h(w_conv[i], wch + (size_t)i * 9 * 128 * 128, 9 * 128 * 128);
    f2h(w_qkv, wqkvh, 3 * 128 * 384);
    f2h(w_ap, waph, 3 * 128 * 128);
    f2h(w1, w1h, (size_t)3 * 384 * 1536);
    f2h(w2, w2h, (size_t)3 * 1536 * 384);
    f2h(wp, wph, 384 * 384);

    // 1. per-branch 2-way gates
    branch_gate_kernel<<<NPIX / 8, 256>>>(x, wg1, wg2, wg3, gates);

    // 2. branches
    for (int br = 0; br < 3; br++) {
        conv_moe_h<<<dim3(3 * HGT, BATCH), 256, CONVH_SMEM_BYTES>>>(
            xh, wch + (size_t)(2 * br) * 9 * 128 * 128, b_conv[2 * br],
            wch + (size_t)(2 * br + 1) * 9 * 128 * 128, b_conv[2 * br + 1],
            gates, br, moeh);
        gemm_h<<<dim3((3 * HDIM) / 128, NPIX / 128), 256, GH_SMEM_BYTES>>>(
            moeh, HDIM, wqkvh + (size_t)br * HDIM * 3 * HDIM, 3 * HDIM,
            nullptr, nullptr, 0, 0, qkv, nullptr, 3 * HDIM, HDIM, 0, 0,
            nullptr, 0, nullptr);
        attn_tc<<<BATCH * HGT, 256, ATTN_SMEM_BYTES>>>(qkv, obufh);
        gemm_h<<<dim3(HDIM / 128, NPIX / 128), 256, GH_SMEM_BYTES>>>(
            obufh, HDIM, waph + (size_t)br * HDIM * HDIM, HDIM,
            b_ap + (size_t)br * HDIM, nullptr, 0, 0,
            xc + br * HDIM, xch + br * HDIM, CH, HDIM, 0, 0,
            nullptr, 0, nullptr);
    }

    // 3. top-2 MoE gates + compaction + padding
    moe_gate_kernel<<<NPIX / 8, 256>>>(xc, wgf, mgate, midx, cnt);
    pad_kernel<<<3, 128>>>(cnt, midx, cntp);

    // 4. sparse 2-of-3 expert MLP (gather rows -> hidden; scatter-accum out)
    for (int e = 0; e < 3; e++) {
        gemm_h<<<dim3(MLPH / 128, NPIX / 128), 256, GH_SMEM_BYTES>>>(
            xch, CH, w1h + (size_t)e * CH * MLPH, MLPH, b1 + (size_t)e * MLPH,
            nullptr, 0, 0, nullptr, hiddenh, MLPH, CH, 1, 0,
            midx + e * NPAD, 1, cntp + e);
        gemm_h<<<dim3(CH / 128, NPIX / 128), 256, GH_SMEM_BYTES>>>(
            hiddenh, MLPH, w2h + (size_t)e * MLPH * CH, CH, b2 + (size_t)e * CH,
            mgate, 3, e, accum, nullptr, CH, MLPH, 0, 1,
            midx + e * NPAD, 0, cntp + e);
    }

    // 5. final projection (accum -> fp16 -> out)
    f2h(accum, accumh, (size_t)NPIX * CH);
    gemm_h<<<dim3(CH / 128, NPIX / 128), 256, GH_SMEM_BYTES>>>(
        accumh, CH, wph, CH, bp, nullptr, 0, 0, out, nullptr, CH, CH, 0, 0,
        nullptr, 0, nullptr);
}